// round 2
// baseline (speedup 1.0000x reference)
#include <cuda_runtime.h>

#define NPTS 1600
#define CIN  256
#define ODIM 256
#define HD   64
#define NH   4
#define STR   68    // normal smem row stride (floats)
#define STRD 132    // duplicated-A smem row stride (floats)

typedef unsigned long long ull;

// packed f32x2 helpers (FFMA2 is not emitted by ptxas from C++; PTX only)
#define FFMA2(acc, a, b) asm("fma.rn.f32x2 %0, %1, %2, %0;" : "+l"(acc) : "l"(a), "l"(b))
#define MUL2(acc, f2)    asm("mul.rn.f32x2 %0, %0, %1;"     : "+l"(acc) : "l"(f2))
#define PACKDUP(d, x)    asm("mov.b64 %0, {%1, %2};" : "=l"(d) : "f"(x), "f"(x))
#define UNPACK(lo, hi, v) asm("mov.b64 {%0, %1}, %2;" : "=f"(lo), "=f"(hi) : "l"(v))

__device__ __align__(16) float g_Q [NH*NPTS*HD];
__device__ __align__(16) float g_K [NH*NPTS*HD];
__device__ __align__(16) float g_V [NH*NPTS*HD];
__device__ __align__(16) float g_Vt[NH*NPTS*HD];
__device__ __align__(16) float g_part[32*NPTS*HD];   // unnormalized O per (pair,split)
__device__ float g_m[32*NPTS];
__device__ float g_l[32*NPTS];

// ---------------------------------------------------------------------------
// QKV projection with FFMA2. grid (25, 4, 3), block 256.
// ---------------------------------------------------------------------------
__global__ __launch_bounds__(256) void proj_kernel(
    const float* __restrict__ x,
    const float* __restrict__ Wq, const float* __restrict__ bq,
    const float* __restrict__ Wk, const float* __restrict__ bk,
    const float* __restrict__ Wv, const float* __restrict__ bv)
{
    const float* W; const float* bias; float* out;
    if (blockIdx.z == 0)      { W = Wq; bias = bq; out = g_Q; }
    else if (blockIdx.z == 1) { W = Wk; bias = bk; out = g_K; }
    else                      { W = Wv; bias = bv; out = g_V; }

    __shared__ float sXTd[32*STRD];   // [c][2n] duplicated
    __shared__ float sWt [32*STR];    // [c][o]

    const int tid = threadIdx.x;
    const int tx = tid & 15, ty = tid >> 4;
    const int n0 = blockIdx.x * 64, o0 = blockIdx.y * 64;

    ull acc2[4][2];
    #pragma unroll
    for (int i = 0; i < 4; i++) { acc2[i][0] = 0ull; acc2[i][1] = 0ull; }

    for (int c0 = 0; c0 < CIN; c0 += 32) {
        #pragma unroll
        for (int it = 0; it < 2; it++) {
            int idx = tid + it*256;
            int r  = idx >> 3;            // n row 0..63
            int cc = (idx & 7) * 4;       // c col
            float4 v = *(const float4*)&x[(n0 + r)*CIN + c0 + cc];
            sXTd[(cc+0)*STRD + 2*r]     = v.x; sXTd[(cc+0)*STRD + 2*r + 1] = v.x;
            sXTd[(cc+1)*STRD + 2*r]     = v.y; sXTd[(cc+1)*STRD + 2*r + 1] = v.y;
            sXTd[(cc+2)*STRD + 2*r]     = v.z; sXTd[(cc+2)*STRD + 2*r + 1] = v.z;
            sXTd[(cc+3)*STRD + 2*r]     = v.w; sXTd[(cc+3)*STRD + 2*r + 1] = v.w;
        }
        #pragma unroll
        for (int it = 0; it < 2; it++) {
            int idx = tid + it*256;
            int r  = idx >> 4;
            int cc = (idx & 15) * 4;
            *(float4*)&sWt[r*STR + cc] = *(const float4*)&W[(c0 + r)*ODIM + o0 + cc];
        }
        __syncthreads();
        #pragma unroll 16
        for (int c = 0; c < 32; c++) {
            ulonglong2 A0 = *(const ulonglong2*)&sXTd[c*STRD + ty*8];
            ulonglong2 A1 = *(const ulonglong2*)&sXTd[c*STRD + ty*8 + 4];
            ulonglong2 B  = *(const ulonglong2*)&sWt [c*STR  + tx*4];
            FFMA2(acc2[0][0], A0.x, B.x); FFMA2(acc2[0][1], A0.x, B.y);
            FFMA2(acc2[1][0], A0.y, B.x); FFMA2(acc2[1][1], A0.y, B.y);
            FFMA2(acc2[2][0], A1.x, B.x); FFMA2(acc2[2][1], A1.x, B.y);
            FFMA2(acc2[3][0], A1.y, B.x); FFMA2(acc2[3][1], A1.y, B.y);
        }
        __syncthreads();
    }

    float bb[4];
    #pragma unroll
    for (int j = 0; j < 4; j++) bb[j] = bias[o0 + tx*4 + j];

    #pragma unroll
    for (int i = 0; i < 4; i++) {
        float vals[4];
        UNPACK(vals[0], vals[1], acc2[i][0]);
        UNPACK(vals[2], vals[3], acc2[i][1]);
        int n = n0 + ty*4 + i;
        #pragma unroll
        for (int j = 0; j < 4; j++) {
            int o = o0 + tx*4 + j;
            int head = o >> 6, dd = o & 63;
            out[(head*NPTS + n)*HD + dd] = vals[j] + bb[j];
        }
    }
}

// ---------------------------------------------------------------------------
// Vtilde[h][j][d] = sum_{s in {-4,-2,0,2,4}} V[h][(j+s) mod N][d]
// ---------------------------------------------------------------------------
__global__ __launch_bounds__(256) void vtilde_kernel()
{
    int idx4 = blockIdx.x * blockDim.x + threadIdx.x;
    int e   = idx4 * 4;
    int h   = e / (NPTS*HD);
    int rem = e - h*(NPTS*HD);
    int j   = rem / HD;
    int dd  = rem - j*HD;

    float4 acc = make_float4(0.f, 0.f, 0.f, 0.f);
    #pragma unroll
    for (int s = -4; s <= 4; s += 2) {
        int jj = j + s;
        if (jj < 0) jj += NPTS;
        if (jj >= NPTS) jj -= NPTS;
        float4 v = *(const float4*)&g_V[(h*NPTS + jj)*HD + dd];
        acc.x += v.x; acc.y += v.y; acc.z += v.z; acc.w += v.w;
    }
    *(float4*)&g_Vt[(h*NPTS + j)*HD + dd] = acc;
}

// ---------------------------------------------------------------------------
// Flash attention, FFMA2 core, split-K over keys (2 splits of 13/12 tiles).
// grid (25, 16, 2), block 256, dynamic smem 102400 B.
// Outputs unnormalized O + per-row (m, l) for log-sum-exp combine.
// ---------------------------------------------------------------------------
__global__ __launch_bounds__(256) void attn_kernel()
{
    extern __shared__ float sm[];
    float* sQTd = sm;                          // [d][2r] duplicated
    float* sPTd = sm + 64*STRD;                // [j][2r] duplicated
    float* sKT  = sm + 2*64*STRD;              // [d][j]
    float* sV   = sm + 2*64*STRD + 64*STR;     // [j][d]

    const int tid = threadIdx.x;
    const int tx = tid & 15, ty = tid >> 4;
    const int qn0 = blockIdx.x * 64;
    const int pair = blockIdx.y;
    const int sp = blockIdx.z;
    const int hq = pair >> 2, kh = pair & 3;
    const int h  = ((hq - kh + 1) & 3) - 1;     // in {-1,0,1,2}
    const int vh = (hq + h + 4) & 3;
    const int kt0 = sp ? 13 : 0;
    const int ktN = sp ? 25 : 13;

    // Load Q tile (scaled by 1/16), transposed + duplicated
    const float* Qb = g_Q + (hq*NPTS + qn0)*HD;
    #pragma unroll
    for (int it = 0; it < 4; it++) {
        int idx = tid + it*256;
        int r  = idx >> 4;
        int dd = (idx & 15) * 4;
        float4 v = *(const float4*)&Qb[r*HD + dd];
        float a0 = v.x * 0.0625f, a1 = v.y * 0.0625f, a2 = v.z * 0.0625f, a3 = v.w * 0.0625f;
        *(float2*)&sQTd[(dd+0)*STRD + 2*r] = make_float2(a0, a0);
        *(float2*)&sQTd[(dd+1)*STRD + 2*r] = make_float2(a1, a1);
        *(float2*)&sQTd[(dd+2)*STRD + 2*r] = make_float2(a2, a2);
        *(float2*)&sQTd[(dd+3)*STRD + 2*r] = make_float2(a3, a3);
    }

    float m_i[4], l_i[4];
    ull o2[4][2];
    #pragma unroll
    for (int i = 0; i < 4; i++) {
        m_i[i] = -1e30f; l_i[i] = 0.f;
        o2[i][0] = 0ull; o2[i][1] = 0ull;
    }

    for (int kt = kt0; kt < ktN; kt++) {
        const float* Kb = g_K  + (kh*NPTS + kt*64)*HD;
        const float* Vb = g_Vt + (vh*NPTS + kt*64)*HD;
        #pragma unroll
        for (int it = 0; it < 4; it++) {
            int idx = tid + it*256;
            int r  = idx >> 4;
            int dd = (idx & 15) * 4;
            float4 kv = *(const float4*)&Kb[r*HD + dd];
            sKT[(dd+0)*STR + r] = kv.x;
            sKT[(dd+1)*STR + r] = kv.y;
            sKT[(dd+2)*STR + r] = kv.z;
            sKT[(dd+3)*STR + r] = kv.w;
            *(float4*)&sV[r*STR + dd] = *(const float4*)&Vb[r*HD + dd];
        }
        __syncthreads();

        // S = Qs @ K^T  (64x64x64), packed
        ull s2[4][2];
        #pragma unroll
        for (int i = 0; i < 4; i++) { s2[i][0] = 0ull; s2[i][1] = 0ull; }
        #pragma unroll 16
        for (int d = 0; d < 64; d++) {
            ulonglong2 A0 = *(const ulonglong2*)&sQTd[d*STRD + ty*8];
            ulonglong2 A1 = *(const ulonglong2*)&sQTd[d*STRD + ty*8 + 4];
            ulonglong2 B  = *(const ulonglong2*)&sKT [d*STR  + tx*4];
            FFMA2(s2[0][0], A0.x, B.x); FFMA2(s2[0][1], A0.x, B.y);
            FFMA2(s2[1][0], A0.y, B.x); FFMA2(s2[1][1], A0.y, B.y);
            FFMA2(s2[2][0], A1.x, B.x); FFMA2(s2[2][1], A1.x, B.y);
            FFMA2(s2[3][0], A1.y, B.x); FFMA2(s2[3][1], A1.y, B.y);
        }

        // Online softmax update
        #pragma unroll
        for (int i = 0; i < 4; i++) {
            float s[4];
            UNPACK(s[0], s[1], s2[i][0]);
            UNPACK(s[2], s[3], s2[i][1]);
            float tm = fmaxf(fmaxf(s[0], s[1]), fmaxf(s[2], s[3]));
            tm = fmaxf(tm, __shfl_xor_sync(0xffffffffu, tm, 1));
            tm = fmaxf(tm, __shfl_xor_sync(0xffffffffu, tm, 2));
            tm = fmaxf(tm, __shfl_xor_sync(0xffffffffu, tm, 4));
            tm = fmaxf(tm, __shfl_xor_sync(0xffffffffu, tm, 8));
            float mn = fmaxf(m_i[i], tm);
            float f  = __expf(m_i[i] - mn);
            m_i[i] = mn;
            float ps = 0.f;
            #pragma unroll
            for (int j = 0; j < 4; j++) {
                s[j] = __expf(s[j] - mn);
                ps += s[j];
            }
            ps += __shfl_xor_sync(0xffffffffu, ps, 1);
            ps += __shfl_xor_sync(0xffffffffu, ps, 2);
            ps += __shfl_xor_sync(0xffffffffu, ps, 4);
            ps += __shfl_xor_sync(0xffffffffu, ps, 8);
            l_i[i] = l_i[i]*f + ps;
            ull ff; PACKDUP(ff, f);
            MUL2(o2[i][0], ff);
            MUL2(o2[i][1], ff);
            // stage P transposed + duplicated: sPTd[j][2r]
            #pragma unroll
            for (int j = 0; j < 4; j++)
                *(float2*)&sPTd[(tx*4 + j)*STRD + 2*(ty*4 + i)] = make_float2(s[j], s[j]);
        }
        __syncthreads();

        // O += P @ Vtilde  (64x64x64), packed
        #pragma unroll 16
        for (int j = 0; j < 64; j++) {
            ulonglong2 A0 = *(const ulonglong2*)&sPTd[j*STRD + ty*8];
            ulonglong2 A1 = *(const ulonglong2*)&sPTd[j*STRD + ty*8 + 4];
            ulonglong2 B  = *(const ulonglong2*)&sV  [j*STR  + tx*4];
            FFMA2(o2[0][0], A0.x, B.x); FFMA2(o2[0][1], A0.x, B.y);
            FFMA2(o2[1][0], A0.y, B.x); FFMA2(o2[1][1], A0.y, B.y);
            FFMA2(o2[2][0], A1.x, B.x); FFMA2(o2[2][1], A1.x, B.y);
            FFMA2(o2[3][0], A1.y, B.x); FFMA2(o2[3][1], A1.y, B.y);
        }
        __syncthreads();
    }

    const int pidx = pair*2 + sp;
    float* op = g_part + (pidx*NPTS + qn0)*HD;
    #pragma unroll
    for (int i = 0; i < 4; i++) {
        float vals[4];
        UNPACK(vals[0], vals[1], o2[i][0]);
        UNPACK(vals[2], vals[3], o2[i][1]);
        #pragma unroll
        for (int j = 0; j < 4; j++)
            op[(ty*4 + i)*HD + tx*4 + j] = vals[j];
        if (tx == 0) {
            g_m[pidx*NPTS + qn0 + ty*4 + i] = m_i[i];
            g_l[pidx*NPTS + qn0 + ty*4 + i] = l_i[i];
        }
    }
}

// ---------------------------------------------------------------------------
// out[n][hq*64+d] = sum_kh wgt * softmax-merge of the 2 splits
// ---------------------------------------------------------------------------
__global__ __launch_bounds__(256) void combine_kernel(float* __restrict__ out)
{
    int idx4 = blockIdx.x * blockDim.x + threadIdx.x;
    int e  = idx4 * 4;
    int n  = e >> 8;
    int o  = e & 255;
    int a  = o >> 6, dd = o & 63;
    float4 acc = make_float4(0.f, 0.f, 0.f, 0.f);
    #pragma unroll
    for (int khh = 0; khh < 4; khh++) {
        int hh = ((a - khh + 1) & 3) - 1;
        float wgt = (hh == 2) ? 2.0f : 1.0f;
        int p0 = (a*4 + khh)*2;
        float m1 = g_m[p0*NPTS + n],     m2 = g_m[(p0+1)*NPTS + n];
        float l1 = g_l[p0*NPTS + n],     l2 = g_l[(p0+1)*NPTS + n];
        float M  = fmaxf(m1, m2);
        float f1 = __expf(m1 - M), f2 = __expf(m2 - M);
        float den = l1*f1 + l2*f2;
        float w1 = wgt * f1 / den, w2 = wgt * f2 / den;
        float4 v1 = *(const float4*)&g_part[(p0*NPTS + n)*HD + dd];
        float4 v2 = *(const float4*)&g_part[((p0+1)*NPTS + n)*HD + dd];
        acc.x += w1*v1.x + w2*v2.x;
        acc.y += w1*v1.y + w2*v2.y;
        acc.z += w1*v1.z + w2*v2.z;
        acc.w += w1*v1.w + w2*v2.w;
    }
    *(float4*)&out[e] = acc;
}

// ---------------------------------------------------------------------------
extern "C" void kernel_launch(void* const* d_in, const int* in_sizes, int n_in,
                              void* d_out, int out_size)
{
    const float* x  = (const float*)d_in[0];
    const float* Wq = (const float*)d_in[1];
    const float* bq = (const float*)d_in[2];
    const float* Wk = (const float*)d_in[3];
    const float* bk = (const float*)d_in[4];
    const float* Wv = (const float*)d_in[5];
    const float* bv = (const float*)d_in[6];
    float* out = (float*)d_out;

    const int smem_bytes = (2*64*STRD + 2*64*STR)*(int)sizeof(float);  // 102400
    cudaFuncSetAttribute(attn_kernel,
                         cudaFuncAttributeMaxDynamicSharedMemorySize, smem_bytes);

    proj_kernel<<<dim3(NPTS/64, ODIM/64, 3), 256>>>(x, Wq, bq, Wk, bk, Wv, bv);
    vtilde_kernel<<<(NH*NPTS*HD/4 + 255)/256, 256>>>();
    attn_kernel<<<dim3(NPTS/64, 16, 2), 256, smem_bytes>>>();
    combine_kernel<<<(NPTS*ODIM/4 + 255)/256, 256>>>(out);
}

// round 4
// speedup vs baseline: 2.9229x; 2.9229x over previous
#include <cuda_runtime.h>

#define NPTS 1600
#define HPAD 1664           // 13*128 padded rows per head
#define CIN  256
#define ODIM 256
#define HD   64
#define NH   4
#define STR  68             // proj smem stride
#define SKS  68             // attn smem stride (floats)
#define NKT  25
#define SCALE_L2E 0.090168439f   // log2(e)/16

__device__ __align__(16) float g_Q [NH*HPAD*HD];
__device__ __align__(16) float g_K [NH*HPAD*HD];
__device__ __align__(16) float g_V [NH*HPAD*HD];
__device__ __align__(16) float g_Vt[NH*HPAD*HD];
__device__ __align__(16) float g_part[16*NPTS*HD];

// m16n8k8 tf32 mma, D==C in-place
#define MMA(c, a, b) \
    asm volatile("mma.sync.aligned.m16n8k8.row.col.f32.tf32.tf32.f32 " \
                 "{%0,%1,%2,%3},{%4,%5,%6,%7},{%8,%9},{%0,%1,%2,%3};" \
                 : "+f"((c)[0]), "+f"((c)[1]), "+f"((c)[2]), "+f"((c)[3]) \
                 : "r"((a)[0]), "r"((a)[1]), "r"((a)[2]), "r"((a)[3]), \
                   "r"((b)[0]), "r"((b)[1]))

#define EX2(d, x) asm("ex2.approx.f32 %0, %1;" : "=f"(d) : "f"(x))

// ---------------------------------------------------------------------------
// QKV projection (scalar, known-good). grid (25,4,3), block 256.
// ---------------------------------------------------------------------------
__global__ __launch_bounds__(256) void proj_kernel(
    const float* __restrict__ x,
    const float* __restrict__ Wq, const float* __restrict__ bq,
    const float* __restrict__ Wk, const float* __restrict__ bk,
    const float* __restrict__ Wv, const float* __restrict__ bv)
{
    const float* W; const float* bias; float* out;
    if (blockIdx.z == 0)      { W = Wq; bias = bq; out = g_Q; }
    else if (blockIdx.z == 1) { W = Wk; bias = bk; out = g_K; }
    else                      { W = Wv; bias = bv; out = g_V; }

    __shared__ float sXT[32*STR];
    __shared__ float sWt[32*STR];

    const int tid = threadIdx.x;
    const int tx = tid & 15, ty = tid >> 4;
    const int n0 = blockIdx.x * 64, o0 = blockIdx.y * 64;

    float acc[4][4] = {};

    for (int c0 = 0; c0 < CIN; c0 += 32) {
        #pragma unroll
        for (int it = 0; it < 2; it++) {
            int idx = tid + it*256;
            int r  = idx >> 3;
            int cc = (idx & 7) * 4;
            float4 v = *(const float4*)&x[(n0 + r)*CIN + c0 + cc];
            sXT[(cc+0)*STR + r] = v.x;
            sXT[(cc+1)*STR + r] = v.y;
            sXT[(cc+2)*STR + r] = v.z;
            sXT[(cc+3)*STR + r] = v.w;
        }
        #pragma unroll
        for (int it = 0; it < 2; it++) {
            int idx = tid + it*256;
            int r  = idx >> 4;
            int cc = (idx & 15) * 4;
            *(float4*)&sWt[r*STR + cc] = *(const float4*)&W[(c0 + r)*ODIM + o0 + cc];
        }
        __syncthreads();
        #pragma unroll 16
        for (int c = 0; c < 32; c++) {
            float4 a = *(float4*)&sXT[c*STR + ty*4];
            float4 b = *(float4*)&sWt[c*STR + tx*4];
            float av[4] = {a.x, a.y, a.z, a.w};
            float bv2[4] = {b.x, b.y, b.z, b.w};
            #pragma unroll
            for (int i = 0; i < 4; i++)
                #pragma unroll
                for (int j = 0; j < 4; j++)
                    acc[i][j] += av[i] * bv2[j];
        }
        __syncthreads();
    }

    #pragma unroll
    for (int j = 0; j < 4; j++) {
        int o = o0 + tx*4 + j;
        float bb = bias[o];
        int head = o >> 6, dd = o & 63;
        #pragma unroll
        for (int i = 0; i < 4; i++) {
            int n = n0 + ty*4 + i;
            out[(head*HPAD + n)*HD + dd] = acc[i][j] + bb;
        }
    }
}

// ---------------------------------------------------------------------------
// Vtilde[h][j][d] = sum_{s in {-4,-2,0,2,4}} V[h][(j+s) mod N][d]
// ---------------------------------------------------------------------------
__global__ __launch_bounds__(256) void vtilde_kernel()
{
    int idx4 = blockIdx.x * blockDim.x + threadIdx.x;
    int e   = idx4 * 4;
    int h   = e / (NPTS*HD);
    int rem = e - h*(NPTS*HD);
    int j   = rem / HD;
    int dd  = rem - j*HD;

    float4 acc = make_float4(0.f, 0.f, 0.f, 0.f);
    #pragma unroll
    for (int s = -4; s <= 4; s += 2) {
        int jj = j + s;
        if (jj < 0) jj += NPTS;
        if (jj >= NPTS) jj -= NPTS;
        float4 v = *(const float4*)&g_V[(h*HPAD + jj)*HD + dd];
        acc.x += v.x; acc.y += v.y; acc.z += v.z; acc.w += v.w;
    }
    *(float4*)&g_Vt[(h*HPAD + j)*HD + dd] = acc;
}

// ---------------------------------------------------------------------------
// mma.sync tf32 flash attention. grid (13, 16), block 256 (8 warps),
// dynamic smem: sK 64x68 + sVT 64x68 + sP 8x(16x68) floats = 69632 B.
// Warp w handles Q rows [qn0 + 16w, qn0 + 16w + 16).
// ---------------------------------------------------------------------------
__global__ __launch_bounds__(256, 2) void attn_kernel()
{
    extern __shared__ float sm[];
    float* sK  = sm;                 // [j][d] stride 68
    float* sVT = sm + 64*SKS;        // [d][j] stride 68
    const int tid = threadIdx.x;
    const int wid = tid >> 5, lane = tid & 31;
    const int g = lane >> 2, tg = lane & 3;
    float* sP = sm + 2*64*SKS + wid*16*SKS;   // per-warp [16][68]

    const int qt = blockIdx.x, pair = blockIdx.y;
    const int hq = pair >> 2, kh = pair & 3;
    const int h  = ((hq - kh + 1) & 3) - 1;      // in {-1,0,1,2}
    const float wgt = (h == 2) ? 2.0f : 1.0f;    // h=+2 and h=-2 fold
    const int vh = (hq + h + 4) & 3;
    const int qn0 = qt * 128, r0 = wid * 16;

    // ---- Q A-fragments (loaded once, pre-scaled by log2e/16) ----
    unsigned qa[8][4];
    {
        const float* Qb = g_Q + (hq*HPAD + qn0 + r0)*HD;
        #pragma unroll
        for (int k0 = 0; k0 < 8; k0++) {
            qa[k0][0] = __float_as_uint(Qb[ g     *HD + k0*8 + tg    ] * SCALE_L2E);
            qa[k0][1] = __float_as_uint(Qb[(g + 8)*HD + k0*8 + tg    ] * SCALE_L2E);
            qa[k0][2] = __float_as_uint(Qb[ g     *HD + k0*8 + tg + 4] * SCALE_L2E);
            qa[k0][3] = __float_as_uint(Qb[(g + 8)*HD + k0*8 + tg + 4] * SCALE_L2E);
        }
    }

    float o[8][4] = {};
    float l0 = 0.f, l1 = 0.f;

    for (int kt = 0; kt < NKT; kt++) {
        __syncthreads();   // prior tile's smem reads complete
        const float* Kb = g_K  + (kh*HPAD + kt*64)*HD;
        const float* Vb = g_Vt + (vh*HPAD + kt*64)*HD;
        #pragma unroll
        for (int it = 0; it < 4; it++) {
            int idx = tid + it*256;
            int j  = idx >> 4, d0 = (idx & 15) << 2;
            *(float4*)&sK[j*SKS + d0] = *(const float4*)&Kb[j*HD + d0];
            int jv = idx & 63, dv = (idx >> 6) << 2;     // conflict-free transpose store
            float4 vv = *(const float4*)&Vb[jv*HD + dv];
            sVT[(dv+0)*SKS + jv] = vv.x;
            sVT[(dv+1)*SKS + jv] = vv.y;
            sVT[(dv+2)*SKS + jv] = vv.z;
            sVT[(dv+3)*SKS + jv] = vv.w;
        }
        __syncthreads();

        // ---- S = Qs @ K^T : 8 k-chunks x 8 n-blocks ----
        float s[8][4] = {};
        #pragma unroll
        for (int k0 = 0; k0 < 8; k0++) {
            #pragma unroll
            for (int n = 0; n < 8; n++) {
                unsigned b[2];
                b[0] = __float_as_uint(sK[(n*8 + g)*SKS + k0*8 + tg    ]);
                b[1] = __float_as_uint(sK[(n*8 + g)*SKS + k0*8 + tg + 4]);
                MMA(s[n], qa[k0], b);
            }
        }

        // ---- exp (base-2, pre-scaled) + P staging (warp-private strip) ----
        #pragma unroll
        for (int n = 0; n < 8; n++) {
            float e0, e1, e2, e3;
            EX2(e0, s[n][0]); EX2(e1, s[n][1]); EX2(e2, s[n][2]); EX2(e3, s[n][3]);
            l0 += e0 + e1;  l1 += e2 + e3;
            *(float2*)&sP[ g     *SKS + n*8 + 2*tg] = make_float2(e0, e1);
            *(float2*)&sP[(g + 8)*SKS + n*8 + 2*tg] = make_float2(e2, e3);
        }
        __syncwarp();

        // ---- O += P @ Vt : 8 k(j)-chunks x 8 n(d)-blocks ----
        #pragma unroll
        for (int k0 = 0; k0 < 8; k0++) {
            unsigned pa[4];
            pa[0] = __float_as_uint(sP[ g     *SKS + k0*8 + tg    ]);
            pa[1] = __float_as_uint(sP[(g + 8)*SKS + k0*8 + tg    ]);
            pa[2] = __float_as_uint(sP[ g     *SKS + k0*8 + tg + 4]);
            pa[3] = __float_as_uint(sP[(g + 8)*SKS + k0*8 + tg + 4]);
            #pragma unroll
            for (int n = 0; n < 8; n++) {
                unsigned b[2];
                b[0] = __float_as_uint(sVT[(n*8 + g)*SKS + k0*8 + tg    ]);
                b[1] = __float_as_uint(sVT[(n*8 + g)*SKS + k0*8 + tg + 4]);
                MMA(o[n], pa, b);
            }
        }
    }

    // ---- epilogue: reduce l over the lane quad, normalize, write ----
    l0 += __shfl_xor_sync(0xffffffffu, l0, 1);
    l0 += __shfl_xor_sync(0xffffffffu, l0, 2);
    l1 += __shfl_xor_sync(0xffffffffu, l1, 1);
    l1 += __shfl_xor_sync(0xffffffffu, l1, 2);
    const float inv0 = wgt / l0, inv1 = wgt / l1;

    const int row0 = qn0 + r0 + g;
    const int row1 = row0 + 8;
    float* op = g_part + (long)pair * NPTS * HD;
    if (row0 < NPTS) {
        #pragma unroll
        for (int n = 0; n < 8; n++)
            *(float2*)&op[row0*HD + n*8 + 2*tg] = make_float2(o[n][0]*inv0, o[n][1]*inv0);
    }
    if (row1 < NPTS) {
        #pragma unroll
        for (int n = 0; n < 8; n++)
            *(float2*)&op[row1*HD + n*8 + 2*tg] = make_float2(o[n][2]*inv1, o[n][3]*inv1);
    }
}

// ---------------------------------------------------------------------------
// out[n][a*64+d] = sum_kh part[a*4+kh][n][d]   (weights already applied)
// ---------------------------------------------------------------------------
__global__ __launch_bounds__(256) void combine_kernel(float* __restrict__ out)
{
    int idx4 = blockIdx.x * blockDim.x + threadIdx.x;
    int e  = idx4 * 4;
    int n  = e >> 8;
    int o  = e & 255;
    int a  = o >> 6, dd = o & 63;
    float4 acc = make_float4(0.f, 0.f, 0.f, 0.f);
    #pragma unroll
    for (int khh = 0; khh < 4; khh++) {
        float4 v = *(const float4*)&g_part[((a*4 + khh)*NPTS + n)*HD + dd];
        acc.x += v.x; acc.y += v.y; acc.z += v.z; acc.w += v.w;
    }
    *(float4*)&out[e] = acc;
}

// ---------------------------------------------------------------------------
extern "C" void kernel_launch(void* const* d_in, const int* in_sizes, int n_in,
                              void* d_out, int out_size)
{
    const float* x  = (const float*)d_in[0];
    const float* Wq = (const float*)d_in[1];
    const float* bq = (const float*)d_in[2];
    const float* Wk = (const float*)d_in[3];
    const float* bk = (const float*)d_in[4];
    const float* Wv = (const float*)d_in[5];
    const float* bv = (const float*)d_in[6];
    float* out = (float*)d_out;

    const int smem_attn = (2*64*SKS + 8*16*SKS) * (int)sizeof(float);  // 69632
    cudaFuncSetAttribute(attn_kernel,
                         cudaFuncAttributeMaxDynamicSharedMemorySize, smem_attn);

    proj_kernel<<<dim3(NPTS/64, ODIM/64, 3), 256>>>(x, Wq, bq, Wk, bk, Wv, bv);
    vtilde_kernel<<<(NH*NPTS*HD/4 + 255)/256, 256>>>();
    attn_kernel<<<dim3(13, 16), 256, smem_attn>>>();
    combine_kernel<<<(NPTS*ODIM/4 + 255)/256, 256>>>(out);
}

// round 5
// speedup vs baseline: 3.4388x; 1.1765x over previous
#include <cuda_runtime.h>
#include <cuda_fp16.h>

#define NPTS 1600
#define HPAD 1664           // 13*128 padded Q rows per head
#define CIN  256
#define ODIM 256
#define HD   64
#define NH   4
#define STR  68             // proj smem stride
#define NKT  25
#define SCALE_L2E 0.090168439f   // log2(e)/16

#define SKW 36              // sK / sP stride in uint (half2) units
#define SVW 36              // sVT stride in uint2 units
#define SK_BYTES  (64*SKW*4)              // 9216
#define SVT_OFF   SK_BYTES                // 9216
#define SVT_BYTES (64*SVW*8)              // 18432
#define SP_OFF    (SVT_OFF + SVT_BYTES)   // 27648
#define SMEM_ATTN (SP_OFF + 8*16*SKW*4)   // 46080

__device__ __align__(16) __half g_Qh[NH*HPAD*HD];
__device__ __align__(16) __half g_Kh[NH*HPAD*HD];
__device__ __align__(16) float  g_V  [NH*HPAD*HD];
__device__ __align__(16) uint2  g_Vt2[NH*NKT*64*32];   // [h][kt][d][jp] -> (vh2, vl2)
__device__ __align__(16) float  g_part[32*NPTS*HD];    // unnormalized O per (pair,split)
__device__ float g_l[32*NPTS];

// m16n8k16 f16 mma, fp32 accumulate, D==C in place
#define MMAH(c, a0, a1, a2, a3, b0, b1) \
    asm volatile("mma.sync.aligned.m16n8k16.row.col.f32.f16.f16.f32 " \
                 "{%0,%1,%2,%3},{%4,%5,%6,%7},{%8,%9},{%0,%1,%2,%3};" \
                 : "+f"((c)[0]), "+f"((c)[1]), "+f"((c)[2]), "+f"((c)[3]) \
                 : "r"(a0), "r"(a1), "r"(a2), "r"(a3), "r"(b0), "r"(b1))

#define EX2(d, x) asm("ex2.approx.f32 %0, %1;" : "=f"(d) : "f"(x))
// d = {hi, lo} packed fp16x2
#define PACKH2(d, lo, hi) asm("cvt.rn.f16x2.f32 %0, %1, %2;" : "=r"(d) : "f"(hi), "f"(lo))

// ---------------------------------------------------------------------------
// QKV projection (scalar fp32 math). grid (25,4,3), block 256.
// z=0 -> Q (half, pre-scaled), z=1 -> K (half), z=2 -> V (float)
// ---------------------------------------------------------------------------
__global__ __launch_bounds__(256) void proj_kernel(
    const float* __restrict__ x,
    const float* __restrict__ Wq, const float* __restrict__ bq,
    const float* __restrict__ Wk, const float* __restrict__ bk,
    const float* __restrict__ Wv, const float* __restrict__ bv)
{
    const float* W; const float* bias;
    const int zb = blockIdx.z;
    if (zb == 0)      { W = Wq; bias = bq; }
    else if (zb == 1) { W = Wk; bias = bk; }
    else              { W = Wv; bias = bv; }

    __shared__ float sXT[32*STR];
    __shared__ float sWt[32*STR];

    const int tid = threadIdx.x;
    const int tx = tid & 15, ty = tid >> 4;
    const int n0 = blockIdx.x * 64, o0 = blockIdx.y * 64;

    float acc[4][4] = {};

    for (int c0 = 0; c0 < CIN; c0 += 32) {
        #pragma unroll
        for (int it = 0; it < 2; it++) {
            int idx = tid + it*256;
            int r  = idx >> 3;
            int cc = (idx & 7) * 4;
            float4 v = *(const float4*)&x[(n0 + r)*CIN + c0 + cc];
            sXT[(cc+0)*STR + r] = v.x;
            sXT[(cc+1)*STR + r] = v.y;
            sXT[(cc+2)*STR + r] = v.z;
            sXT[(cc+3)*STR + r] = v.w;
        }
        #pragma unroll
        for (int it = 0; it < 2; it++) {
            int idx = tid + it*256;
            int r  = idx >> 4;
            int cc = (idx & 15) * 4;
            *(float4*)&sWt[r*STR + cc] = *(const float4*)&W[(c0 + r)*ODIM + o0 + cc];
        }
        __syncthreads();
        #pragma unroll 16
        for (int c = 0; c < 32; c++) {
            float4 a = *(float4*)&sXT[c*STR + ty*4];
            float4 b = *(float4*)&sWt[c*STR + tx*4];
            float av[4] = {a.x, a.y, a.z, a.w};
            float bv2[4] = {b.x, b.y, b.z, b.w};
            #pragma unroll
            for (int i = 0; i < 4; i++)
                #pragma unroll
                for (int j = 0; j < 4; j++)
                    acc[i][j] += av[i] * bv2[j];
        }
        __syncthreads();
    }

    #pragma unroll
    for (int j = 0; j < 4; j++) {
        int o = o0 + tx*4 + j;
        float bb = bias[o];
        int head = o >> 6, dd = o & 63;
        #pragma unroll
        for (int i = 0; i < 4; i++) {
            int n = n0 + ty*4 + i;
            float val = acc[i][j] + bb;
            long idx = (long)(head*HPAD + n)*HD + dd;
            if (zb == 0)      g_Qh[idx] = __float2half_rn(val * SCALE_L2E);
            else if (zb == 1) g_Kh[idx] = __float2half_rn(val);
            else              g_V [idx] = val;
        }
    }
}

// ---------------------------------------------------------------------------
// Vtilde: per (h, kt, jp, d4) compute 5-shift sums for j=2jp,2jp+1 over 4 d's,
// split into fp16 hi/lo planes, store in attn's transposed tile layout.
// 51200 threads.
// ---------------------------------------------------------------------------
__global__ __launch_bounds__(256) void vtilde_kernel()
{
    int idx = blockIdx.x * 256 + threadIdx.x;
    if (idx >= NH*NKT*32*16) return;
    int d4  = idx & 15;
    int jp  = (idx >> 4) & 31;
    int kt  = (idx >> 9) % NKT;
    int h   = idx / (NKT*512);

    int j0 = kt*64 + 2*jp;
    float4 a0 = make_float4(0.f,0.f,0.f,0.f);
    float4 a1 = make_float4(0.f,0.f,0.f,0.f);
    #pragma unroll
    for (int s = -4; s <= 4; s += 2) {
        int jj0 = j0 + s;     if (jj0 < 0) jj0 += NPTS; else if (jj0 >= NPTS) jj0 -= NPTS;
        int jj1 = j0 + 1 + s; if (jj1 < 0) jj1 += NPTS; else if (jj1 >= NPTS) jj1 -= NPTS;
        float4 v0 = *(const float4*)&g_V[(h*HPAD + jj0)*HD + d4*4];
        float4 v1 = *(const float4*)&g_V[(h*HPAD + jj1)*HD + d4*4];
        a0.x += v0.x; a0.y += v0.y; a0.z += v0.z; a0.w += v0.w;
        a1.x += v1.x; a1.y += v1.y; a1.z += v1.z; a1.w += v1.w;
    }
    float v0a[4] = {a0.x, a0.y, a0.z, a0.w};
    float v1a[4] = {a1.x, a1.y, a1.z, a1.w};
    #pragma unroll
    for (int i = 0; i < 4; i++) {
        __half h0 = __float2half_rn(v0a[i]);
        __half l0h = __float2half_rn(v0a[i] - __half2float(h0));
        __half h1 = __float2half_rn(v1a[i]);
        __half l1h = __float2half_rn(v1a[i] - __half2float(h1));
        __half2 hh = __halves2half2(h0, h1);   // lo = j even
        __half2 ll = __halves2half2(l0h, l1h);
        g_Vt2[(((h*NKT + kt)*64) + d4*4 + i)*32 + jp] =
            make_uint2(*(unsigned*)&hh, *(unsigned*)&ll);
    }
}

// ---------------------------------------------------------------------------
// fp16 mma.sync flash attention, split-K. grid (13, 16, 2), block 256.
// Split sp handles key tiles [sp?13:0, sp?25:13). No max-subtraction, so the
// split merge in combine is a plain sum of (unnormalized O, l).
// ---------------------------------------------------------------------------
__global__ __launch_bounds__(256, 2) void attn_kernel()
{
    extern __shared__ char smem[];
    unsigned* sK  = (unsigned*)smem;                  // [j][dp] half2 words
    uint2*    sVT = (uint2*)(smem + SVT_OFF);         // [d][jp] (vh2, vl2)
    const int tid = threadIdx.x;
    const int wid = tid >> 5, lane = tid & 31;
    const int g = lane >> 2, tg = lane & 3;
    unsigned* sPw = (unsigned*)(smem + SP_OFF) + wid*16*SKW;

    const int qt = blockIdx.x, pair = blockIdx.y, sp = blockIdx.z;
    const int hq = pair >> 2, kh = pair & 3;
    const int h  = ((hq - kh + 1) & 3) - 1;      // in {-1,0,1,2}
    const int vh = (hq + h + 4) & 3;
    const int qn0 = qt * 128, r0 = wid * 16;
    const int kt0 = sp ? 13 : 0, ktN = sp ? 25 : 13;
    const int pidx = pair*2 + sp;

    // ---- Q fragments (half2 words), loaded once from global ----
    unsigned qa[4][4];
    {
        const unsigned* Qg = (const unsigned*)g_Qh + (hq*HPAD + qn0 + r0)*32;
        #pragma unroll
        for (int kc = 0; kc < 4; kc++) {
            qa[kc][0] = Qg[ g     *32 + kc*8 + tg    ];
            qa[kc][1] = Qg[(g + 8)*32 + kc*8 + tg    ];
            qa[kc][2] = Qg[ g     *32 + kc*8 + tg + 4];
            qa[kc][3] = Qg[(g + 8)*32 + kc*8 + tg + 4];
        }
    }

    float o[8][4] = {};
    float l0 = 0.f, l1 = 0.f;

    const uint4* Kg = (const uint4*)g_Kh  + (long)kh*HPAD*8;      // 8 uint4 / row
    const uint4* Vg = (const uint4*)g_Vt2 + (long)vh*NKT*64*16;   // 16 uint4 / row

    for (int kt = kt0; kt < ktN; kt++) {
        __syncthreads();
        // ---- stage K (512 uint4) and VT (1024 uint4) ----
        {
            const uint4* Kt = Kg + kt*64*8;
            #pragma unroll
            for (int it = 0; it < 2; it++) {
                int i4 = tid + it*256;
                int j = i4 >> 3, c = i4 & 7;
                *(uint4*)&sK[j*SKW + c*4] = Kt[j*8 + c];
            }
            const uint4* Vt = Vg + (kt - kt0 + kt0)*64*16;  // = Vg + kt*64*16
            #pragma unroll
            for (int it = 0; it < 4; it++) {
                int i4 = tid + it*256;
                int d = i4 >> 4, c = i4 & 15;
                *(uint4*)&sVT[d*SVW + c*2] = Vt[d*16 + c];
            }
        }
        __syncthreads();

        // ---- S = Qs @ K^T : 4 k16-chunks x 8 n-blocks ----
        float s[8][4] = {};
        #pragma unroll
        for (int kc = 0; kc < 4; kc++) {
            #pragma unroll
            for (int n = 0; n < 8; n++) {
                unsigned b0 = sK[(n*8 + g)*SKW + kc*8 + tg    ];
                unsigned b1 = sK[(n*8 + g)*SKW + kc*8 + tg + 4];
                MMAH(s[n], qa[kc][0], qa[kc][1], qa[kc][2], qa[kc][3], b0, b1);
            }
        }

        // ---- exp2 (pre-scaled, no max-sub) + fp16 pack + warp-private stage ----
        #pragma unroll
        for (int n = 0; n < 8; n++) {
            float e0, e1, e2, e3;
            EX2(e0, s[n][0]); EX2(e1, s[n][1]); EX2(e2, s[n][2]); EX2(e3, s[n][3]);
            l0 += e0 + e1;  l1 += e2 + e3;
            unsigned p0, p1;
            PACKH2(p0, e0, e1);
            PACKH2(p1, e2, e3);
            sPw[ g     *SKW + n*4 + tg] = p0;
            sPw[(g + 8)*SKW + n*4 + tg] = p1;
        }
        __syncwarp();

        // ---- O += P @ (Vh + Vl) : 4 k-chunks x 8 n-blocks x 2 planes ----
        #pragma unroll
        for (int kc = 0; kc < 4; kc++) {
            unsigned pa0 = sPw[ g     *SKW + kc*8 + tg    ];
            unsigned pa1 = sPw[(g + 8)*SKW + kc*8 + tg    ];
            unsigned pa2 = sPw[ g     *SKW + kc*8 + tg + 4];
            unsigned pa3 = sPw[(g + 8)*SKW + kc*8 + tg + 4];
            #pragma unroll
            for (int n = 0; n < 8; n++) {
                uint2 b0 = sVT[(n*8 + g)*SVW + kc*8 + tg    ];
                uint2 b1 = sVT[(n*8 + g)*SVW + kc*8 + tg + 4];
                MMAH(o[n], pa0, pa1, pa2, pa3, b0.x, b1.x);
                MMAH(o[n], pa0, pa1, pa2, pa3, b0.y, b1.y);
            }
        }
    }

    // ---- epilogue: quad-reduce l, write unnormalized O + l ----
    l0 += __shfl_xor_sync(0xffffffffu, l0, 1);
    l0 += __shfl_xor_sync(0xffffffffu, l0, 2);
    l1 += __shfl_xor_sync(0xffffffffu, l1, 1);
    l1 += __shfl_xor_sync(0xffffffffu, l1, 2);

    const int row0 = qn0 + r0 + g;
    const int row1 = row0 + 8;
    float* op = g_part + (long)pidx * NPTS * HD;
    if (row0 < NPTS) {
        #pragma unroll
        for (int n = 0; n < 8; n++)
            *(float2*)&op[row0*HD + n*8 + 2*tg] = make_float2(o[n][0], o[n][1]);
        if (tg == 0) g_l[pidx*NPTS + row0] = l0;
    }
    if (row1 < NPTS) {
        #pragma unroll
        for (int n = 0; n < 8; n++)
            *(float2*)&op[row1*HD + n*8 + 2*tg] = make_float2(o[n][2], o[n][3]);
        if (tg == 0) g_l[pidx*NPTS + row1] = l1;
    }
}

// ---------------------------------------------------------------------------
// out[n][a*64+d] = sum_kh wgt * (O_s0 + O_s1) / (l_s0 + l_s1)
// ---------------------------------------------------------------------------
__global__ __launch_bounds__(256) void combine_kernel(float* __restrict__ out)
{
    int idx4 = blockIdx.x * blockDim.x + threadIdx.x;
    int e  = idx4 * 4;
    int n  = e >> 8;
    int o  = e & 255;
    int a  = o >> 6, dd = o & 63;
    float4 acc = make_float4(0.f, 0.f, 0.f, 0.f);
    #pragma unroll
    for (int khh = 0; khh < 4; khh++) {
        int hh = ((a - khh + 1) & 3) - 1;
        float wgt = (hh == 2) ? 2.0f : 1.0f;
        int p0 = (a*4 + khh)*2;
        float l = g_l[p0*NPTS + n] + g_l[(p0+1)*NPTS + n];
        float w = wgt / l;
        float4 v1 = *(const float4*)&g_part[((long)p0*NPTS + n)*HD + dd];
        float4 v2 = *(const float4*)&g_part[((long)(p0+1)*NPTS + n)*HD + dd];
        acc.x += w*(v1.x + v2.x);
        acc.y += w*(v1.y + v2.y);
        acc.z += w*(v1.z + v2.z);
        acc.w += w*(v1.w + v2.w);
    }
    *(float4*)&out[e] = acc;
}

// ---------------------------------------------------------------------------
extern "C" void kernel_launch(void* const* d_in, const int* in_sizes, int n_in,
                              void* d_out, int out_size)
{
    const float* x  = (const float*)d_in[0];
    const float* Wq = (const float*)d_in[1];
    const float* bq = (const float*)d_in[2];
    const float* Wk = (const float*)d_in[3];
    const float* bk = (const float*)d_in[4];
    const float* Wv = (const float*)d_in[5];
    const float* bv = (const float*)d_in[6];
    float* out = (float*)d_out;

    cudaFuncSetAttribute(attn_kernel,
                         cudaFuncAttributeMaxDynamicSharedMemorySize, SMEM_ATTN);

    proj_kernel<<<dim3(NPTS/64, ODIM/64, 3), 256>>>(x, Wq, bq, Wk, bk, Wv, bv);
    vtilde_kernel<<<(NH*NKT*32*16 + 255)/256, 256>>>();
    attn_kernel<<<dim3(13, 16, 2), 256, SMEM_ATTN>>>();
    combine_kernel<<<(NPTS*ODIM/4 + 255)/256, 256>>>(out);
}

// round 6
// speedup vs baseline: 7.6018x; 2.2106x over previous
#include <cuda_runtime.h>
#include <cuda_fp16.h>

#define NPTS 1600
#define HPAD 1664           // 13*128 padded Q rows per head
#define CIN  256
#define ODIM 256
#define HD   64
#define NH   4
#define STR  68             // proj smem stride
#define NKT  25
#define SCALE_L2E 0.090168439f   // log2(e)/16

#define SKB   144                 // smem row stride bytes (64 halves + pad)
#define TILEB (64*SKB)            // 9216 per tile
#define SMEM_ATTN (4*TILEB)       // K0,K1,V0,V1 = 36864

__device__ __align__(16) __half g_Qh[NH*HPAD*HD];
__device__ __align__(16) __half g_Kh[NH*HPAD*HD];
__device__ __align__(16) float  g_V  [NH*HPAD*HD];
__device__ __align__(16) unsigned g_Vt[NH*NKT*64*32];  // [h][kt][d][jp] half2
__device__ __align__(16) float  g_part[32*NPTS*HD];    // unnormalized O per (pair,split)
__device__ float g_l[32*NPTS];

// m16n8k16 f16 mma, fp32 accumulate, D==C in place
#define MMAH(c, a0, a1, a2, a3, b0, b1) \
    asm volatile("mma.sync.aligned.m16n8k16.row.col.f32.f16.f16.f32 " \
                 "{%0,%1,%2,%3},{%4,%5,%6,%7},{%8,%9},{%0,%1,%2,%3};" \
                 : "+f"((c)[0]), "+f"((c)[1]), "+f"((c)[2]), "+f"((c)[3]) \
                 : "r"(a0), "r"(a1), "r"(a2), "r"(a3), "r"(b0), "r"(b1))

#define LDSM4(r0, r1, r2, r3, a) \
    asm volatile("ldmatrix.sync.aligned.m8n8.x4.shared.b16 {%0,%1,%2,%3}, [%4];" \
                 : "=r"(r0), "=r"(r1), "=r"(r2), "=r"(r3) : "r"(a))

#define EX2(d, x) asm("ex2.approx.f32 %0, %1;" : "=f"(d) : "f"(x))
#define PACKH2(d, lo, hi) asm("cvt.rn.f16x2.f32 %0, %1, %2;" : "=r"(d) : "f"(hi), "f"(lo))
#define CPA16(dst, src) \
    asm volatile("cp.async.cg.shared.global [%0], [%1], 16;" :: "r"(dst), "l"(src))
#define CPA_COMMIT() asm volatile("cp.async.commit_group;")
#define CPA_WAIT1()  asm volatile("cp.async.wait_group 1;")
#define CPA_WAIT0()  asm volatile("cp.async.wait_group 0;")

__device__ __forceinline__ unsigned smem_u32(const void* p) {
    unsigned a;
    asm("{ .reg .u64 t; cvta.to.shared.u64 t, %1; cvt.u32.u64 %0, t; }"
        : "=r"(a) : "l"(p));
    return a;
}

// ---------------------------------------------------------------------------
// QKV projection (scalar fp32 math). grid (25,4,3), block 256.
// z=0 -> Q (half, pre-scaled), z=1 -> K (half), z=2 -> V (float)
// ---------------------------------------------------------------------------
__global__ __launch_bounds__(256) void proj_kernel(
    const float* __restrict__ x,
    const float* __restrict__ Wq, const float* __restrict__ bq,
    const float* __restrict__ Wk, const float* __restrict__ bk,
    const float* __restrict__ Wv, const float* __restrict__ bv)
{
    const float* W; const float* bias;
    const int zb = blockIdx.z;
    if (zb == 0)      { W = Wq; bias = bq; }
    else if (zb == 1) { W = Wk; bias = bk; }
    else              { W = Wv; bias = bv; }

    __shared__ float sXT[32*STR];
    __shared__ float sWt[32*STR];

    const int tid = threadIdx.x;
    const int tx = tid & 15, ty = tid >> 4;
    const int n0 = blockIdx.x * 64, o0 = blockIdx.y * 64;

    float acc[4][4] = {};

    for (int c0 = 0; c0 < CIN; c0 += 32) {
        #pragma unroll
        for (int it = 0; it < 2; it++) {
            int idx = tid + it*256;
            int r  = idx >> 3;
            int cc = (idx & 7) * 4;
            float4 v = *(const float4*)&x[(n0 + r)*CIN + c0 + cc];
            sXT[(cc+0)*STR + r] = v.x;
            sXT[(cc+1)*STR + r] = v.y;
            sXT[(cc+2)*STR + r] = v.z;
            sXT[(cc+3)*STR + r] = v.w;
        }
        #pragma unroll
        for (int it = 0; it < 2; it++) {
            int idx = tid + it*256;
            int r  = idx >> 4;
            int cc = (idx & 15) * 4;
            *(float4*)&sWt[r*STR + cc] = *(const float4*)&W[(c0 + r)*ODIM + o0 + cc];
        }
        __syncthreads();
        #pragma unroll 16
        for (int c = 0; c < 32; c++) {
            float4 a = *(float4*)&sXT[c*STR + ty*4];
            float4 b = *(float4*)&sWt[c*STR + tx*4];
            float av[4] = {a.x, a.y, a.z, a.w};
            float bv2[4] = {b.x, b.y, b.z, b.w};
            #pragma unroll
            for (int i = 0; i < 4; i++)
                #pragma unroll
                for (int j = 0; j < 4; j++)
                    acc[i][j] += av[i] * bv2[j];
        }
        __syncthreads();
    }

    #pragma unroll
    for (int j = 0; j < 4; j++) {
        int o = o0 + tx*4 + j;
        float bb = bias[o];
        int head = o >> 6, dd = o & 63;
        #pragma unroll
        for (int i = 0; i < 4; i++) {
            int n = n0 + ty*4 + i;
            float val = acc[i][j] + bb;
            long idx = (long)(head*HPAD + n)*HD + dd;
            if (zb == 0)      g_Qh[idx] = __float2half_rn(val * SCALE_L2E);
            else if (zb == 1) g_Kh[idx] = __float2half_rn(val);
            else              g_V [idx] = val;
        }
    }
}

// ---------------------------------------------------------------------------
// Vtilde: 5-shift circular sums of V, fp16, stored transposed per key-tile:
// g_Vt[h][kt][d][jp] = half2( Vt(j=2jp), Vt(j=2jp+1) )
// ---------------------------------------------------------------------------
__global__ __launch_bounds__(256) void vtilde_kernel()
{
    int idx = blockIdx.x * 256 + threadIdx.x;
    if (idx >= NH*NKT*32*16) return;
    int d4  = idx & 15;
    int jp  = (idx >> 4) & 31;
    int kt  = (idx >> 9) % NKT;
    int h   = idx / (NKT*512);

    int j0 = kt*64 + 2*jp;
    float4 a0 = make_float4(0.f,0.f,0.f,0.f);
    float4 a1 = make_float4(0.f,0.f,0.f,0.f);
    #pragma unroll
    for (int s = -4; s <= 4; s += 2) {
        int jj0 = j0 + s;     if (jj0 < 0) jj0 += NPTS; else if (jj0 >= NPTS) jj0 -= NPTS;
        int jj1 = j0 + 1 + s; if (jj1 < 0) jj1 += NPTS; else if (jj1 >= NPTS) jj1 -= NPTS;
        float4 v0 = *(const float4*)&g_V[(h*HPAD + jj0)*HD + d4*4];
        float4 v1 = *(const float4*)&g_V[(h*HPAD + jj1)*HD + d4*4];
        a0.x += v0.x; a0.y += v0.y; a0.z += v0.z; a0.w += v0.w;
        a1.x += v1.x; a1.y += v1.y; a1.z += v1.z; a1.w += v1.w;
    }
    float v0a[4] = {a0.x, a0.y, a0.z, a0.w};
    float v1a[4] = {a1.x, a1.y, a1.z, a1.w};
    #pragma unroll
    for (int i = 0; i < 4; i++) {
        __half2 hh = __floats2half2_rn(v0a[i], v1a[i]);   // lo = j even
        g_Vt[(((h*NKT + kt)*64) + d4*4 + i)*32 + jp] = *(unsigned*)&hh;
    }
}

// ---------------------------------------------------------------------------
// fp16 mma.sync flash attention, register-resident P, ldmatrix B-frags,
// cp.async double-buffered tiles, split-K. grid (13, 16, 2), block 256.
// ---------------------------------------------------------------------------
__global__ __launch_bounds__(256, 2) void attn_kernel()
{
    extern __shared__ char smem[];
    const unsigned sbase = smem_u32(smem);
    const int tid = threadIdx.x;
    const int wid = tid >> 5, lane = tid & 31;
    const int g = lane >> 2, tg = lane & 3;

    const int qt = blockIdx.x, pair = blockIdx.y, sp = blockIdx.z;
    const int hq = pair >> 2, kh = pair & 3;
    const int h  = ((hq - kh + 1) & 3) - 1;      // in {-1,0,1,2}
    const int vh = (hq + h + 4) & 3;
    const int qn0 = qt * 128, r0 = wid * 16;
    const int kt0 = sp ? 13 : 0, ktN = sp ? 25 : 13;
    const int pidx = pair*2 + sp;

    // ldmatrix per-lane base offset within a tile buffer
    const unsigned lmb = (unsigned)(((lane & 7) + ((lane & 16) >> 1))*SKB
                                    + ((lane & 8) ? 16 : 0));

    // ---- Q fragments (half2 words), loaded once from global ----
    unsigned qa[4][4];
    {
        const unsigned* Qg = (const unsigned*)g_Qh + (hq*HPAD + qn0 + r0)*32;
        #pragma unroll
        for (int kc = 0; kc < 4; kc++) {
            qa[kc][0] = Qg[ g     *32 + kc*8 + tg    ];
            qa[kc][1] = Qg[(g + 8)*32 + kc*8 + tg    ];
            qa[kc][2] = Qg[ g     *32 + kc*8 + tg + 4];
            qa[kc][3] = Qg[(g + 8)*32 + kc*8 + tg + 4];
        }
    }

    const uint4* Kg = (const uint4*)g_Kh + (long)kh*HPAD*8;       // 8 uint4 / row
    const uint4* Vg = (const uint4*)g_Vt + (long)vh*NKT*64*8;     // 8 uint4 / row

    // stage tile kt into buffer b (K at b*TILEB, V at (2+b)*TILEB)
    auto stage = [&](int kt, int b) {
        const uint4* Kt = Kg + kt*64*8;
        const uint4* Vt = Vg + kt*64*8;
        unsigned kd = sbase + b*TILEB;
        unsigned vd = sbase + (2 + b)*TILEB;
        #pragma unroll
        for (int it = 0; it < 2; it++) {
            int i4 = tid + it*256;
            unsigned off = (unsigned)((i4 >> 3)*SKB + (i4 & 7)*16);
            CPA16(kd + off, (unsigned long long)__cvta_generic_to_global(Kt + i4));
            CPA16(vd + off, (unsigned long long)__cvta_generic_to_global(Vt + i4));
        }
    };

    float o[8][4] = {};
    float l0 = 0.f, l1 = 0.f;

    stage(kt0, 0);
    CPA_COMMIT();

    for (int kt = kt0; kt < ktN; kt++) {
        const int c = (kt - kt0) & 1;
        if (kt + 1 < ktN) {
            stage(kt + 1, c ^ 1);
            CPA_COMMIT();
            CPA_WAIT1();
        } else {
            CPA_WAIT0();
        }
        __syncthreads();

        const unsigned kadr = sbase + c*TILEB + lmb;
        const unsigned vadr = sbase + (2 + c)*TILEB + lmb;

        // ---- S = Qs @ K^T ----
        float s[8][4] = {};
        #pragma unroll
        for (int kc = 0; kc < 4; kc++) {
            #pragma unroll
            for (int np = 0; np < 4; np++) {
                unsigned b0, b1, b2, b3;
                LDSM4(b0, b1, b2, b3, kadr + np*(16*SKB) + kc*32);
                MMAH(s[2*np],   qa[kc][0], qa[kc][1], qa[kc][2], qa[kc][3], b0, b1);
                MMAH(s[2*np+1], qa[kc][0], qa[kc][1], qa[kc][2], qa[kc][3], b2, b3);
            }
        }

        // ---- exp2 (pre-scaled, no max-sub); P stays in registers ----
        unsigned p0[8], p1[8];
        #pragma unroll
        for (int n = 0; n < 8; n++) {
            float e0, e1, e2, e3;
            EX2(e0, s[n][0]); EX2(e1, s[n][1]); EX2(e2, s[n][2]); EX2(e3, s[n][3]);
            l0 += e0 + e1;  l1 += e2 + e3;
            PACKH2(p0[n], e0, e1);    // {P[g][n*8+2tg], P[g][n*8+2tg+1]}
            PACKH2(p1[n], e2, e3);    // row g+8
        }

        // ---- O += P @ Vt (C-frags of S are the A-frags of PV) ----
        #pragma unroll
        for (int kc = 0; kc < 4; kc++) {
            #pragma unroll
            for (int np = 0; np < 4; np++) {
                unsigned b0, b1, b2, b3;
                LDSM4(b0, b1, b2, b3, vadr + np*(16*SKB) + kc*32);
                MMAH(o[2*np],   p0[2*kc], p1[2*kc], p0[2*kc+1], p1[2*kc+1], b0, b1);
                MMAH(o[2*np+1], p0[2*kc], p1[2*kc], p0[2*kc+1], p1[2*kc+1], b2, b3);
            }
        }
        __syncthreads();   // all warps done reading buffer c before it is refilled
    }

    // ---- epilogue: quad-reduce l, write unnormalized O + l ----
    l0 += __shfl_xor_sync(0xffffffffu, l0, 1);
    l0 += __shfl_xor_sync(0xffffffffu, l0, 2);
    l1 += __shfl_xor_sync(0xffffffffu, l1, 1);
    l1 += __shfl_xor_sync(0xffffffffu, l1, 2);

    const int row0 = qn0 + r0 + g;
    const int row1 = row0 + 8;
    float* op = g_part + (long)pidx * NPTS * HD;
    if (row0 < NPTS) {
        #pragma unroll
        for (int n = 0; n < 8; n++)
            *(float2*)&op[row0*HD + n*8 + 2*tg] = make_float2(o[n][0], o[n][1]);
        if (tg == 0) g_l[pidx*NPTS + row0] = l0;
    }
    if (row1 < NPTS) {
        #pragma unroll
        for (int n = 0; n < 8; n++)
            *(float2*)&op[row1*HD + n*8 + 2*tg] = make_float2(o[n][2], o[n][3]);
        if (tg == 0) g_l[pidx*NPTS + row1] = l1;
    }
}

// ---------------------------------------------------------------------------
// out[n][a*64+d] = sum_kh wgt * (O_s0 + O_s1) / (l_s0 + l_s1)
// ---------------------------------------------------------------------------
__global__ __launch_bounds__(256) void combine_kernel(float* __restrict__ out)
{
    int idx4 = blockIdx.x * blockDim.x + threadIdx.x;
    int e  = idx4 * 4;
    int n  = e >> 8;
    int o  = e & 255;
    int a  = o >> 6, dd = o & 63;
    float4 acc = make_float4(0.f, 0.f, 0.f, 0.f);
    #pragma unroll
    for (int khh = 0; khh < 4; khh++) {
        int hh = ((a - khh + 1) & 3) - 1;
        float wgt = (hh == 2) ? 2.0f : 1.0f;
        int p0 = (a*4 + khh)*2;
        float l = g_l[p0*NPTS + n] + g_l[(p0+1)*NPTS + n];
        float w = wgt / l;
        float4 v1 = *(const float4*)&g_part[((long)p0*NPTS + n)*HD + dd];
        float4 v2 = *(const float4*)&g_part[((long)(p0+1)*NPTS + n)*HD + dd];
        acc.x += w*(v1.x + v2.x);
        acc.y += w*(v1.y + v2.y);
        acc.z += w*(v1.z + v2.z);
        acc.w += w*(v1.w + v2.w);
    }
    *(float4*)&out[e] = acc;
}

// ---------------------------------------------------------------------------
extern "C" void kernel_launch(void* const* d_in, const int* in_sizes, int n_in,
                              void* d_out, int out_size)
{
    const float* x  = (const float*)d_in[0];
    const float* Wq = (const float*)d_in[1];
    const float* bq = (const float*)d_in[2];
    const float* Wk = (const float*)d_in[3];
    const float* bk = (const float*)d_in[4];
    const float* Wv = (const float*)d_in[5];
    const float* bv = (const float*)d_in[6];
    float* out = (float*)d_out;

    cudaFuncSetAttribute(attn_kernel,
                         cudaFuncAttributeMaxDynamicSharedMemorySize, SMEM_ATTN);

    proj_kernel<<<dim3(NPTS/64, ODIM/64, 3), 256>>>(x, Wq, bq, Wk, bk, Wv, bv);
    vtilde_kernel<<<(NH*NKT*32*16 + 255)/256, 256>>>();
    attn_kernel<<<dim3(13, 16, 2), 256, SMEM_ATTN>>>();
    combine_kernel<<<(NPTS*ODIM/4 + 255)/256, 256>>>(out);
}

// round 7
// speedup vs baseline: 8.6735x; 1.1410x over previous
#include <cuda_runtime.h>
#include <cuda_fp16.h>

#define NPTS 1600
#define HPAD 1664           // 13*128 padded rows per head
#define CIN  256
#define ODIM 256
#define HD   64
#define NH   4
#define NKT  25
#define SCALE_L2E 0.090168439f   // log2(e)/16

#define SKB   144                 // attn smem row stride bytes
#define TILEB (64*SKB)            // 9216 per tile
#define SMEM_ATTN (4*TILEB)       // 36864

#define PAB   144                 // proj smem row stride bytes
#define PA_OFF 0                  // A tile 128 x 64 halves
#define PB_OFF (128*PAB)          // 18432, B tile 64 x 64 halves
#define ONES_H2 0x3C003C00u

__device__ __align__(16) __half g_xh [HPAD*CIN];       // fp16 x, zero-padded rows
__device__ __align__(16) __half g_WhT[3*ODIM*CIN];     // [z][o][c] transposed fp16 W
__device__ __align__(16) __half g_Qh[NH*HPAD*HD];
__device__ __align__(16) __half g_Kh[NH*HPAD*HD];
__device__ __align__(16) float  g_V  [NH*HPAD*HD];
__device__ __align__(16) unsigned g_Vt[NH*NKT*64*32];  // [h][kt][d][jp] half2
__device__ __align__(16) float  g_part[32*NPTS*HD];
__device__ float g_l[32*NPTS];

#define MMAH(c, a0, a1, a2, a3, b0, b1) \
    asm volatile("mma.sync.aligned.m16n8k16.row.col.f32.f16.f16.f32 " \
                 "{%0,%1,%2,%3},{%4,%5,%6,%7},{%8,%9},{%0,%1,%2,%3};" \
                 : "+f"((c)[0]), "+f"((c)[1]), "+f"((c)[2]), "+f"((c)[3]) \
                 : "r"(a0), "r"(a1), "r"(a2), "r"(a3), "r"(b0), "r"(b1))

#define LDSM4(r0, r1, r2, r3, a) \
    asm volatile("ldmatrix.sync.aligned.m8n8.x4.shared.b16 {%0,%1,%2,%3}, [%4];" \
                 : "=r"(r0), "=r"(r1), "=r"(r2), "=r"(r3) : "r"(a))

#define EX2(d, x) asm("ex2.approx.f32 %0, %1;" : "=f"(d) : "f"(x))
#define PACKH2(d, lo, hi) asm("cvt.rn.f16x2.f32 %0, %1, %2;" : "=r"(d) : "f"(hi), "f"(lo))
#define CPA16(dst, src) \
    asm volatile("cp.async.cg.shared.global [%0], [%1], 16;" :: "r"(dst), "l"(src))
#define CPA_COMMIT() asm volatile("cp.async.commit_group;")
#define CPA_WAIT1()  asm volatile("cp.async.wait_group 1;")
#define CPA_WAIT0()  asm volatile("cp.async.wait_group 0;")

__device__ __forceinline__ unsigned smem_u32(const void* p) {
    unsigned a;
    asm("{ .reg .u64 t; cvta.to.shared.u64 t, %1; cvt.u32.u64 %0, t; }"
        : "=r"(a) : "l"(p));
    return a;
}

// ---------------------------------------------------------------------------
// convert: x -> fp16 (row layout), W{q,k,v} -> fp16 transposed [o][c]
// 75776 threads.
// ---------------------------------------------------------------------------
__global__ __launch_bounds__(256) void convert_kernel(
    const float* __restrict__ x,
    const float* __restrict__ Wq, const float* __restrict__ Wk,
    const float* __restrict__ Wv)
{
    int id = blockIdx.x * 256 + threadIdx.x;
    if (id < NPTS*CIN/8) {
        int base = id * 8;
        float4 v0 = *(const float4*)&x[base];
        float4 v1 = *(const float4*)&x[base + 4];
        __half2 h0 = __floats2half2_rn(v0.x, v0.y);
        __half2 h1 = __floats2half2_rn(v0.z, v0.w);
        __half2 h2 = __floats2half2_rn(v1.x, v1.y);
        __half2 h3 = __floats2half2_rn(v1.z, v1.w);
        uint4 u = make_uint4(*(unsigned*)&h0, *(unsigned*)&h1,
                             *(unsigned*)&h2, *(unsigned*)&h3);
        *(uint4*)&g_xh[base] = u;
    } else if (id < NPTS*CIN/8 + 3*ODIM*32) {
        int t  = id - NPTS*CIN/8;
        int o  = t & 255;
        int c8 = (t >> 8) & 31;
        int z  = t >> 13;
        const float* W = (z == 0) ? Wq : (z == 1) ? Wk : Wv;
        __half tmp[8];
        #pragma unroll
        for (int i = 0; i < 8; i++)
            tmp[i] = __float2half_rn(W[(c8*8 + i)*ODIM + o]);
        *(uint4*)&g_WhT[(z*ODIM + o)*CIN + c8*8] = *(uint4*)tmp;
    }
}

// ---------------------------------------------------------------------------
// QKV projection via fp16 mma. grid (13, 4, 3), block 256 (8 warps).
// BM=128 (rows qn0..qn0+127), BN=64 (one head slice), K in 4 chunks of 64.
// z=0 -> Q (half, pre-scaled), z=1 -> K (half), z=2 -> V (float)
// ---------------------------------------------------------------------------
__global__ __launch_bounds__(256) void proj_kernel(
    const float* __restrict__ bq, const float* __restrict__ bk,
    const float* __restrict__ bv)
{
    __shared__ __align__(16) char ps[PB_OFF + 64*PAB];
    const unsigned sbase = smem_u32(ps);
    const int tid = threadIdx.x;
    const int wid = tid >> 5, lane = tid & 31;
    const int g = lane >> 2, tg = lane & 3;
    const int zb = blockIdx.z;
    const int qn0 = blockIdx.x * 128, o0 = blockIdx.y * 64;
    const float* bias = (zb == 0) ? bq : (zb == 1) ? bk : bv;

    const unsigned abase = sbase + PA_OFF + (wid*16 + (lane & 15))*PAB
                           + ((lane & 16) ? 16 : 0);
    const unsigned bbase = sbase + PB_OFF + ((lane & 7) + ((lane & 16) >> 1))*PAB
                           + ((lane & 8) ? 16 : 0);

    float c[8][4] = {};

    for (int kc4 = 0; kc4 < 4; kc4++) {
        __syncthreads();
        // stage A (1024 uint4) and B (512 uint4)
        #pragma unroll
        for (int it = 0; it < 4; it++) {
            int i4 = tid + it*256;
            int row = i4 >> 3, cs = i4 & 7;
            *(uint4*)(ps + PA_OFF + row*PAB + cs*16) =
                *(const uint4*)&g_xh[(qn0 + row)*CIN + kc4*64 + cs*8];
        }
        #pragma unroll
        for (int it = 0; it < 2; it++) {
            int i4 = tid + it*256;
            int row = i4 >> 3, cs = i4 & 7;
            *(uint4*)(ps + PB_OFF + row*PAB + cs*16) =
                *(const uint4*)&g_WhT[(zb*ODIM + o0 + row)*CIN + kc4*64 + cs*8];
        }
        __syncthreads();

        #pragma unroll
        for (int k16 = 0; k16 < 4; k16++) {
            unsigned a0, a1, a2, a3;
            LDSM4(a0, a1, a2, a3, abase + k16*32);
            #pragma unroll
            for (int np = 0; np < 4; np++) {
                unsigned b0, b1, b2, b3;
                LDSM4(b0, b1, b2, b3, bbase + np*(16*PAB) + k16*32);
                MMAH(c[2*np],   a0, a1, a2, a3, b0, b1);
                MMAH(c[2*np+1], a0, a1, a2, a3, b2, b3);
            }
        }
    }

    // epilogue: bias, convert, store
    const int row0 = qn0 + wid*16 + g;
    const int row1 = row0 + 8;
    const int head = blockIdx.y;
    #pragma unroll
    for (int n = 0; n < 8; n++) {
        int col = n*8 + 2*tg;
        float b0f = bias[o0 + col], b1f = bias[o0 + col + 1];
        float x0 = c[n][0] + b0f, x1 = c[n][1] + b1f;   // row0
        float x2 = c[n][2] + b0f, x3 = c[n][3] + b1f;   // row1
        if (zb == 0) {
            __half2 h0 = __floats2half2_rn(x0*SCALE_L2E, x1*SCALE_L2E);
            __half2 h1 = __floats2half2_rn(x2*SCALE_L2E, x3*SCALE_L2E);
            if (row0 < NPTS) *(unsigned*)&g_Qh[(head*HPAD + row0)*HD + col] = *(unsigned*)&h0;
            if (row1 < NPTS) *(unsigned*)&g_Qh[(head*HPAD + row1)*HD + col] = *(unsigned*)&h1;
        } else if (zb == 1) {
            __half2 h0 = __floats2half2_rn(x0, x1);
            __half2 h1 = __floats2half2_rn(x2, x3);
            if (row0 < NPTS) *(unsigned*)&g_Kh[(head*HPAD + row0)*HD + col] = *(unsigned*)&h0;
            if (row1 < NPTS) *(unsigned*)&g_Kh[(head*HPAD + row1)*HD + col] = *(unsigned*)&h1;
        } else {
            if (row0 < NPTS) *(float2*)&g_V[(head*HPAD + row0)*HD + col] = make_float2(x0, x1);
            if (row1 < NPTS) *(float2*)&g_V[(head*HPAD + row1)*HD + col] = make_float2(x2, x3);
        }
    }
}

// ---------------------------------------------------------------------------
// Vtilde: 5-shift circular sums of V, fp16, stored transposed per key-tile.
// ---------------------------------------------------------------------------
__global__ __launch_bounds__(256) void vtilde_kernel()
{
    int idx = blockIdx.x * 256 + threadIdx.x;
    if (idx >= NH*NKT*32*16) return;
    int d4  = idx & 15;
    int jp  = (idx >> 4) & 31;
    int kt  = (idx >> 9) % NKT;
    int h   = idx / (NKT*512);

    int j0 = kt*64 + 2*jp;
    float4 a0 = make_float4(0.f,0.f,0.f,0.f);
    float4 a1 = make_float4(0.f,0.f,0.f,0.f);
    #pragma unroll
    for (int s = -4; s <= 4; s += 2) {
        int jj0 = j0 + s;     if (jj0 < 0) jj0 += NPTS; else if (jj0 >= NPTS) jj0 -= NPTS;
        int jj1 = j0 + 1 + s; if (jj1 < 0) jj1 += NPTS; else if (jj1 >= NPTS) jj1 -= NPTS;
        float4 v0 = *(const float4*)&g_V[(h*HPAD + jj0)*HD + d4*4];
        float4 v1 = *(const float4*)&g_V[(h*HPAD + jj1)*HD + d4*4];
        a0.x += v0.x; a0.y += v0.y; a0.z += v0.z; a0.w += v0.w;
        a1.x += v1.x; a1.y += v1.y; a1.z += v1.z; a1.w += v1.w;
    }
    float v0a[4] = {a0.x, a0.y, a0.z, a0.w};
    float v1a[4] = {a1.x, a1.y, a1.z, a1.w};
    #pragma unroll
    for (int i = 0; i < 4; i++) {
        __half2 hh = __floats2half2_rn(v0a[i], v1a[i]);   // lo = j even
        g_Vt[(((h*NKT + kt)*64) + d4*4 + i)*32 + jp] = *(unsigned*)&hh;
    }
}

// ---------------------------------------------------------------------------
// fp16 mma.sync flash attention, register-resident P, ldmatrix B-frags,
// cp.async double-buffer, MMA-based l, split-K. grid (13, 16, 2), block 256.
// ---------------------------------------------------------------------------
__global__ __launch_bounds__(256, 2) void attn_kernel()
{
    extern __shared__ char smem[];
    const unsigned sbase = smem_u32(smem);
    const int tid = threadIdx.x;
    const int wid = tid >> 5, lane = tid & 31;
    const int g = lane >> 2, tg = lane & 3;

    const int qt = blockIdx.x, pair = blockIdx.y, sp = blockIdx.z;
    const int hq = pair >> 2, kh = pair & 3;
    const int h  = ((hq - kh + 1) & 3) - 1;      // in {-1,0,1,2}
    const int vh = (hq + h + 4) & 3;
    const int qn0 = qt * 128, r0 = wid * 16;
    const int kt0 = sp ? 13 : 0, ktN = sp ? 25 : 13;
    const int pidx = pair*2 + sp;

    const unsigned lmb = (unsigned)(((lane & 7) + ((lane & 16) >> 1))*SKB
                                    + ((lane & 8) ? 16 : 0));

    // ---- Q fragments, loaded once ----
    unsigned qa[4][4];
    {
        const unsigned* Qg = (const unsigned*)g_Qh + (hq*HPAD + qn0 + r0)*32;
        #pragma unroll
        for (int kc = 0; kc < 4; kc++) {
            qa[kc][0] = Qg[ g     *32 + kc*8 + tg    ];
            qa[kc][1] = Qg[(g + 8)*32 + kc*8 + tg    ];
            qa[kc][2] = Qg[ g     *32 + kc*8 + tg + 4];
            qa[kc][3] = Qg[(g + 8)*32 + kc*8 + tg + 4];
        }
    }

    const uint4* Kg = (const uint4*)g_Kh + (long)kh*HPAD*8;
    const uint4* Vg = (const uint4*)g_Vt + (long)vh*NKT*64*8;

    auto stage = [&](int kt, int b) {
        const uint4* Kt = Kg + kt*64*8;
        const uint4* Vt = Vg + kt*64*8;
        unsigned kd = sbase + b*TILEB;
        unsigned vd = sbase + (2 + b)*TILEB;
        #pragma unroll
        for (int it = 0; it < 2; it++) {
            int i4 = tid + it*256;
            unsigned off = (unsigned)((i4 >> 3)*SKB + (i4 & 7)*16);
            CPA16(kd + off, (unsigned long long)__cvta_generic_to_global(Kt + i4));
            CPA16(vd + off, (unsigned long long)__cvta_generic_to_global(Vt + i4));
        }
    };

    float o[8][4] = {};
    float lacc[4] = {};

    stage(kt0, 0);
    CPA_COMMIT();

    for (int kt = kt0; kt < ktN; kt++) {
        const int c = (kt - kt0) & 1;
        if (kt + 1 < ktN) {
            stage(kt + 1, c ^ 1);
            CPA_COMMIT();
            CPA_WAIT1();
        } else {
            CPA_WAIT0();
        }
        __syncthreads();

        const unsigned kadr = sbase + c*TILEB + lmb;
        const unsigned vadr = sbase + (2 + c)*TILEB + lmb;

        // ---- S = Qs @ K^T ----
        float s[8][4] = {};
        #pragma unroll
        for (int kc = 0; kc < 4; kc++) {
            #pragma unroll
            for (int np = 0; np < 4; np++) {
                unsigned b0, b1, b2, b3;
                LDSM4(b0, b1, b2, b3, kadr + np*(16*SKB) + kc*32);
                MMAH(s[2*np],   qa[kc][0], qa[kc][1], qa[kc][2], qa[kc][3], b0, b1);
                MMAH(s[2*np+1], qa[kc][0], qa[kc][1], qa[kc][2], qa[kc][3], b2, b3);
            }
        }

        // ---- exp2 (pre-scaled, no max-sub); P stays in registers ----
        unsigned p0[8], p1[8];
        #pragma unroll
        for (int n = 0; n < 8; n++) {
            float e0, e1, e2, e3;
            EX2(e0, s[n][0]); EX2(e1, s[n][1]); EX2(e2, s[n][2]); EX2(e3, s[n][3]);
            PACKH2(p0[n], e0, e1);
            PACKH2(p1[n], e2, e3);
        }

        // ---- O += P @ Vt ; l += P @ 1 ----
        #pragma unroll
        for (int kc = 0; kc < 4; kc++) {
            #pragma unroll
            for (int np = 0; np < 4; np++) {
                unsigned b0, b1, b2, b3;
                LDSM4(b0, b1, b2, b3, vadr + np*(16*SKB) + kc*32);
                MMAH(o[2*np],   p0[2*kc], p1[2*kc], p0[2*kc+1], p1[2*kc+1], b0, b1);
                MMAH(o[2*np+1], p0[2*kc], p1[2*kc], p0[2*kc+1], p1[2*kc+1], b2, b3);
            }
            MMAH(lacc, p0[2*kc], p1[2*kc], p0[2*kc+1], p1[2*kc+1], ONES_H2, ONES_H2);
        }
        __syncthreads();
    }

    // ---- epilogue: write unnormalized O + l (lacc already full row sums) ----
    const int row0 = qn0 + r0 + g;
    const int row1 = row0 + 8;
    float* op = g_part + (long)pidx * NPTS * HD;
    if (row0 < NPTS) {
        #pragma unroll
        for (int n = 0; n < 8; n++)
            *(float2*)&op[row0*HD + n*8 + 2*tg] = make_float2(o[n][0], o[n][1]);
        if (tg == 0) g_l[pidx*NPTS + row0] = lacc[0];
    }
    if (row1 < NPTS) {
        #pragma unroll
        for (int n = 0; n < 8; n++)
            *(float2*)&op[row1*HD + n*8 + 2*tg] = make_float2(o[n][2], o[n][3]);
        if (tg == 0) g_l[pidx*NPTS + row1] = lacc[2];
    }
}

// ---------------------------------------------------------------------------
// out[n][a*64+d] = sum_kh wgt * (O_s0 + O_s1) / (l_s0 + l_s1)
// ---------------------------------------------------------------------------
__global__ __launch_bounds__(256) void combine_kernel(float* __restrict__ out)
{
    int idx4 = blockIdx.x * blockDim.x + threadIdx.x;
    int e  = idx4 * 4;
    int n  = e >> 8;
    int o  = e & 255;
    int a  = o >> 6, dd = o & 63;
    float4 acc = make_float4(0.f, 0.f, 0.f, 0.f);
    #pragma unroll
    for (int khh = 0; khh < 4; khh++) {
        int hh = ((a - khh + 1) & 3) - 1;
        float wgt = (hh == 2) ? 2.0f : 1.0f;
        int p0 = (a*4 + khh)*2;
        float l = g_l[p0*NPTS + n] + g_l[(p0+1)*NPTS + n];
        float w = wgt / l;
        float4 v1 = *(const float4*)&g_part[((long)p0*NPTS + n)*HD + dd];
        float4 v2 = *(const float4*)&g_part[((long)(p0+1)*NPTS + n)*HD + dd];
        acc.x += w*(v1.x + v2.x);
        acc.y += w*(v1.y + v2.y);
        acc.z += w*(v1.z + v2.z);
        acc.w += w*(v1.w + v2.w);
    }
    *(float4*)&out[e] = acc;
}

// ---------------------------------------------------------------------------
extern "C" void kernel_launch(void* const* d_in, const int* in_sizes, int n_in,
                              void* d_out, int out_size)
{
    const float* x  = (const float*)d_in[0];
    const float* Wq = (const float*)d_in[1];
    const float* bq = (const float*)d_in[2];
    const float* Wk = (const float*)d_in[3];
    const float* bk = (const float*)d_in[4];
    const float* Wv = (const float*)d_in[5];
    const float* bv = (const float*)d_in[6];
    float* out = (float*)d_out;

    cudaFuncSetAttribute(attn_kernel,
                         cudaFuncAttributeMaxDynamicSharedMemorySize, SMEM_ATTN);

    convert_kernel<<<(NPTS*CIN/8 + 3*ODIM*32 + 255)/256, 256>>>(x, Wq, Wk, Wv);
    proj_kernel<<<dim3(13, 4, 3), 256>>>(bq, bk, bv);
    vtilde_kernel<<<(NH*NKT*32*16 + 255)/256, 256>>>();
    attn_kernel<<<dim3(13, 16, 2), 256, SMEM_ATTN>>>();
    combine_kernel<<<(NPTS*ODIM/4 + 255)/256, 256>>>(out);
}

// round 8
// speedup vs baseline: 9.0452x; 1.0429x over previous
#include <cuda_runtime.h>
#include <cuda_fp16.h>

#define NPTS 1600
#define HPAD 1664           // 13*128 padded rows per head
#define CIN  256
#define ODIM 256
#define HD   64
#define NH   4
#define NKT  25
#define SCALE_L2E 0.090168439f   // log2(e)/16

#define SKB   144                 // attn smem row stride bytes
#define TILEB (64*SKB)            // 9216 per tile
#define SMEM_ATTN (4*TILEB)       // 36864

#define PAB   144                 // proj smem row stride bytes
#define PA_OFF 0                  // A tile 128 x 64 halves
#define PB_OFF (128*PAB)          // 18432, B tile 64 x 64 halves
#define ONES_H2 0x3C003C00u

__device__ __align__(16) __half g_xh [HPAD*CIN];       // fp16 x, zero-padded rows
__device__ __align__(16) __half g_WhT[3*ODIM*CIN];     // [z][o][c] transposed fp16 W
__device__ __align__(16) __half g_Qh[NH*HPAD*HD];
__device__ __align__(16) __half g_Kh[NH*HPAD*HD];
__device__ __align__(16) float  g_V  [NH*HPAD*HD];
__device__ __align__(16) unsigned g_Vt[NH*NKT*64*32];  // [h][kt][d][jp] half2
__device__ __align__(16) unsigned g_part[32*NPTS*32];  // half2 unnormalized O
__device__ float g_l[32*NPTS];

#define MMAH(c, a0, a1, a2, a3, b0, b1) \
    asm volatile("mma.sync.aligned.m16n8k16.row.col.f32.f16.f16.f32 " \
                 "{%0,%1,%2,%3},{%4,%5,%6,%7},{%8,%9},{%0,%1,%2,%3};" \
                 : "+f"((c)[0]), "+f"((c)[1]), "+f"((c)[2]), "+f"((c)[3]) \
                 : "r"(a0), "r"(a1), "r"(a2), "r"(a3), "r"(b0), "r"(b1))

#define LDSM4(r0, r1, r2, r3, a) \
    asm volatile("ldmatrix.sync.aligned.m8n8.x4.shared.b16 {%0,%1,%2,%3}, [%4];" \
                 : "=r"(r0), "=r"(r1), "=r"(r2), "=r"(r3) : "r"(a))

#define PACKH2(d, lo, hi) asm("cvt.rn.f16x2.f32 %0, %1, %2;" : "=r"(d) : "f"(hi), "f"(lo))
#define EX2H2(d) asm("ex2.approx.f16x2 %0, %0;" : "+r"(d))
#define CPA16(dst, src) \
    asm volatile("cp.async.cg.shared.global [%0], [%1], 16;" :: "r"(dst), "l"(src))
#define CPA_COMMIT() asm volatile("cp.async.commit_group;")
#define CPA_WAIT1()  asm volatile("cp.async.wait_group 1;")
#define CPA_WAIT0()  asm volatile("cp.async.wait_group 0;")

__device__ __forceinline__ unsigned smem_u32(const void* p) {
    unsigned a;
    asm("{ .reg .u64 t; cvta.to.shared.u64 t, %1; cvt.u32.u64 %0, t; }"
        : "=r"(a) : "l"(p));
    return a;
}

// ---------------------------------------------------------------------------
// convert: x -> fp16 (row layout), W{q,k,v} -> fp16 transposed [o][c]
// ---------------------------------------------------------------------------
__global__ __launch_bounds__(256) void convert_kernel(
    const float* __restrict__ x,
    const float* __restrict__ Wq, const float* __restrict__ Wk,
    const float* __restrict__ Wv)
{
    int id = blockIdx.x * 256 + threadIdx.x;
    if (id < NPTS*CIN/8) {
        int base = id * 8;
        float4 v0 = *(const float4*)&x[base];
        float4 v1 = *(const float4*)&x[base + 4];
        __half2 h0 = __floats2half2_rn(v0.x, v0.y);
        __half2 h1 = __floats2half2_rn(v0.z, v0.w);
        __half2 h2 = __floats2half2_rn(v1.x, v1.y);
        __half2 h3 = __floats2half2_rn(v1.z, v1.w);
        uint4 u = make_uint4(*(unsigned*)&h0, *(unsigned*)&h1,
                             *(unsigned*)&h2, *(unsigned*)&h3);
        *(uint4*)&g_xh[base] = u;
    } else if (id < NPTS*CIN/8 + 3*ODIM*32) {
        int t  = id - NPTS*CIN/8;
        int o  = t & 255;
        int c8 = (t >> 8) & 31;
        int z  = t >> 13;
        const float* W = (z == 0) ? Wq : (z == 1) ? Wk : Wv;
        __half tmp[8];
        #pragma unroll
        for (int i = 0; i < 8; i++)
            tmp[i] = __float2half_rn(W[(c8*8 + i)*ODIM + o]);
        *(uint4*)&g_WhT[(z*ODIM + o)*CIN + c8*8] = *(uint4*)tmp;
    }
}

// ---------------------------------------------------------------------------
// QKV projection via fp16 mma. grid (13, 4, 3), block 256 (8 warps).
// ---------------------------------------------------------------------------
__global__ __launch_bounds__(256) void proj_kernel(
    const float* __restrict__ bq, const float* __restrict__ bk,
    const float* __restrict__ bv)
{
    __shared__ __align__(16) char ps[PB_OFF + 64*PAB];
    const unsigned sbase = smem_u32(ps);
    const int tid = threadIdx.x;
    const int wid = tid >> 5, lane = tid & 31;
    const int g = lane >> 2, tg = lane & 3;
    const int zb = blockIdx.z;
    const int qn0 = blockIdx.x * 128, o0 = blockIdx.y * 64;
    const float* bias = (zb == 0) ? bq : (zb == 1) ? bk : bv;

    const unsigned abase = sbase + PA_OFF + (wid*16 + (lane & 15))*PAB
                           + ((lane & 16) ? 16 : 0);
    const unsigned bbase = sbase + PB_OFF + ((lane & 7) + ((lane & 16) >> 1))*PAB
                           + ((lane & 8) ? 16 : 0);

    float c[8][4] = {};

    for (int kc4 = 0; kc4 < 4; kc4++) {
        __syncthreads();
        #pragma unroll
        for (int it = 0; it < 4; it++) {
            int i4 = tid + it*256;
            int row = i4 >> 3, cs = i4 & 7;
            *(uint4*)(ps + PA_OFF + row*PAB + cs*16) =
                *(const uint4*)&g_xh[(qn0 + row)*CIN + kc4*64 + cs*8];
        }
        #pragma unroll
        for (int it = 0; it < 2; it++) {
            int i4 = tid + it*256;
            int row = i4 >> 3, cs = i4 & 7;
            *(uint4*)(ps + PB_OFF + row*PAB + cs*16) =
                *(const uint4*)&g_WhT[(zb*ODIM + o0 + row)*CIN + kc4*64 + cs*8];
        }
        __syncthreads();

        #pragma unroll
        for (int k16 = 0; k16 < 4; k16++) {
            unsigned a0, a1, a2, a3;
            LDSM4(a0, a1, a2, a3, abase + k16*32);
            #pragma unroll
            for (int np = 0; np < 4; np++) {
                unsigned b0, b1, b2, b3;
                LDSM4(b0, b1, b2, b3, bbase + np*(16*PAB) + k16*32);
                MMAH(c[2*np],   a0, a1, a2, a3, b0, b1);
                MMAH(c[2*np+1], a0, a1, a2, a3, b2, b3);
            }
        }
    }

    const int row0 = qn0 + wid*16 + g;
    const int row1 = row0 + 8;
    const int head = blockIdx.y;
    #pragma unroll
    for (int n = 0; n < 8; n++) {
        int col = n*8 + 2*tg;
        float b0f = bias[o0 + col], b1f = bias[o0 + col + 1];
        float x0 = c[n][0] + b0f, x1 = c[n][1] + b1f;   // row0
        float x2 = c[n][2] + b0f, x3 = c[n][3] + b1f;   // row1
        if (zb == 0) {
            __half2 h0 = __floats2half2_rn(x0*SCALE_L2E, x1*SCALE_L2E);
            __half2 h1 = __floats2half2_rn(x2*SCALE_L2E, x3*SCALE_L2E);
            if (row0 < NPTS) *(unsigned*)&g_Qh[(head*HPAD + row0)*HD + col] = *(unsigned*)&h0;
            if (row1 < NPTS) *(unsigned*)&g_Qh[(head*HPAD + row1)*HD + col] = *(unsigned*)&h1;
        } else if (zb == 1) {
            __half2 h0 = __floats2half2_rn(x0, x1);
            __half2 h1 = __floats2half2_rn(x2, x3);
            if (row0 < NPTS) *(unsigned*)&g_Kh[(head*HPAD + row0)*HD + col] = *(unsigned*)&h0;
            if (row1 < NPTS) *(unsigned*)&g_Kh[(head*HPAD + row1)*HD + col] = *(unsigned*)&h1;
        } else {
            if (row0 < NPTS) *(float2*)&g_V[(head*HPAD + row0)*HD + col] = make_float2(x0, x1);
            if (row1 < NPTS) *(float2*)&g_V[(head*HPAD + row1)*HD + col] = make_float2(x2, x3);
        }
    }
}

// ---------------------------------------------------------------------------
// Vtilde: 5-shift circular sums of V, fp16, stored transposed per key-tile.
// ---------------------------------------------------------------------------
__global__ __launch_bounds__(256) void vtilde_kernel()
{
    int idx = blockIdx.x * 256 + threadIdx.x;
    if (idx >= NH*NKT*32*16) return;
    int d4  = idx & 15;
    int jp  = (idx >> 4) & 31;
    int kt  = (idx >> 9) % NKT;
    int h   = idx / (NKT*512);

    int j0 = kt*64 + 2*jp;
    float4 a0 = make_float4(0.f,0.f,0.f,0.f);
    float4 a1 = make_float4(0.f,0.f,0.f,0.f);
    #pragma unroll
    for (int s = -4; s <= 4; s += 2) {
        int jj0 = j0 + s;     if (jj0 < 0) jj0 += NPTS; else if (jj0 >= NPTS) jj0 -= NPTS;
        int jj1 = j0 + 1 + s; if (jj1 < 0) jj1 += NPTS; else if (jj1 >= NPTS) jj1 -= NPTS;
        float4 v0 = *(const float4*)&g_V[(h*HPAD + jj0)*HD + d4*4];
        float4 v1 = *(const float4*)&g_V[(h*HPAD + jj1)*HD + d4*4];
        a0.x += v0.x; a0.y += v0.y; a0.z += v0.z; a0.w += v0.w;
        a1.x += v1.x; a1.y += v1.y; a1.z += v1.z; a1.w += v1.w;
    }
    float v0a[4] = {a0.x, a0.y, a0.z, a0.w};
    float v1a[4] = {a1.x, a1.y, a1.z, a1.w};
    #pragma unroll
    for (int i = 0; i < 4; i++) {
        __half2 hh = __floats2half2_rn(v0a[i], v1a[i]);   // lo = j even
        g_Vt[(((h*NKT + kt)*64) + d4*4 + i)*32 + jp] = *(unsigned*)&hh;
    }
}

// ---------------------------------------------------------------------------
// fp16 mma.sync flash attention, register P, ldmatrix, cp.async double-buffer,
// packed f16x2 ex2, MMA-based l, split-K. grid (13, 16, 2), block 256.
// ---------------------------------------------------------------------------
__global__ __launch_bounds__(256, 2) void attn_kernel()
{
    extern __shared__ char smem[];
    const unsigned sbase = smem_u32(smem);
    const int tid = threadIdx.x;
    const int wid = tid >> 5, lane = tid & 31;
    const int g = lane >> 2, tg = lane & 3;

    const int qt = blockIdx.x, pair = blockIdx.y, sp = blockIdx.z;
    const int hq = pair >> 2, kh = pair & 3;
    const int h  = ((hq - kh + 1) & 3) - 1;      // in {-1,0,1,2}
    const int vh = (hq + h + 4) & 3;
    const int qn0 = qt * 128, r0 = wid * 16;
    const int kt0 = sp ? 13 : 0, ktN = sp ? 25 : 13;
    const int pidx = pair*2 + sp;

    const unsigned lmb = (unsigned)(((lane & 7) + ((lane & 16) >> 1))*SKB
                                    + ((lane & 8) ? 16 : 0));

    // ---- Q fragments, loaded once ----
    unsigned qa[4][4];
    {
        const unsigned* Qg = (const unsigned*)g_Qh + (hq*HPAD + qn0 + r0)*32;
        #pragma unroll
        for (int kc = 0; kc < 4; kc++) {
            qa[kc][0] = Qg[ g     *32 + kc*8 + tg    ];
            qa[kc][1] = Qg[(g + 8)*32 + kc*8 + tg    ];
            qa[kc][2] = Qg[ g     *32 + kc*8 + tg + 4];
            qa[kc][3] = Qg[(g + 8)*32 + kc*8 + tg + 4];
        }
    }

    const uint4* Kg = (const uint4*)g_Kh + (long)kh*HPAD*8;
    const uint4* Vg = (const uint4*)g_Vt + (long)vh*NKT*64*8;

    auto stage = [&](int kt, int b) {
        const uint4* Kt = Kg + kt*64*8;
        const uint4* Vt = Vg + kt*64*8;
        unsigned kd = sbase + b*TILEB;
        unsigned vd = sbase + (2 + b)*TILEB;
        #pragma unroll
        for (int it = 0; it < 2; it++) {
            int i4 = tid + it*256;
            unsigned off = (unsigned)((i4 >> 3)*SKB + (i4 & 7)*16);
            CPA16(kd + off, (unsigned long long)__cvta_generic_to_global(Kt + i4));
            CPA16(vd + off, (unsigned long long)__cvta_generic_to_global(Vt + i4));
        }
    };

    float o[8][4] = {};
    float lacc[4] = {};

    stage(kt0, 0);
    CPA_COMMIT();

    for (int kt = kt0; kt < ktN; kt++) {
        const int c = (kt - kt0) & 1;
        if (kt + 1 < ktN) {
            stage(kt + 1, c ^ 1);
            CPA_COMMIT();
            CPA_WAIT1();
        } else {
            CPA_WAIT0();
        }
        __syncthreads();

        const unsigned kadr = sbase + c*TILEB + lmb;
        const unsigned vadr = sbase + (2 + c)*TILEB + lmb;

        // ---- S = Qs @ K^T ----
        float s[8][4] = {};
        #pragma unroll
        for (int kc = 0; kc < 4; kc++) {
            #pragma unroll
            for (int np = 0; np < 4; np++) {
                unsigned b0, b1, b2, b3;
                LDSM4(b0, b1, b2, b3, kadr + np*(16*SKB) + kc*32);
                MMAH(s[2*np],   qa[kc][0], qa[kc][1], qa[kc][2], qa[kc][3], b0, b1);
                MMAH(s[2*np+1], qa[kc][0], qa[kc][1], qa[kc][2], qa[kc][3], b2, b3);
            }
        }

        // ---- packed f16x2 exp2 (pre-scaled, no max-sub); P in registers ----
        unsigned p0[8], p1[8];
        #pragma unroll
        for (int n = 0; n < 8; n++) {
            PACKH2(p0[n], s[n][0], s[n][1]);
            PACKH2(p1[n], s[n][2], s[n][3]);
            EX2H2(p0[n]);
            EX2H2(p1[n]);
        }

        // ---- O += P @ Vt ; l += P @ 1 ----
        #pragma unroll
        for (int kc = 0; kc < 4; kc++) {
            #pragma unroll
            for (int np = 0; np < 4; np++) {
                unsigned b0, b1, b2, b3;
                LDSM4(b0, b1, b2, b3, vadr + np*(16*SKB) + kc*32);
                MMAH(o[2*np],   p0[2*kc], p1[2*kc], p0[2*kc+1], p1[2*kc+1], b0, b1);
                MMAH(o[2*np+1], p0[2*kc], p1[2*kc], p0[2*kc+1], p1[2*kc+1], b2, b3);
            }
            MMAH(lacc, p0[2*kc], p1[2*kc], p0[2*kc+1], p1[2*kc+1], ONES_H2, ONES_H2);
        }
        __syncthreads();
    }

    // ---- epilogue: write unnormalized O (fp16) + l ----
    const int row0 = qn0 + r0 + g;
    const int row1 = row0 + 8;
    unsigned* op = g_part + (long)pidx * NPTS * 32;
    if (row0 < NPTS) {
        #pragma unroll
        for (int n = 0; n < 8; n++) {
            unsigned u; PACKH2(u, o[n][0], o[n][1]);
            op[row0*32 + n*4 + tg] = u;
        }
        if (tg == 0) g_l[pidx*NPTS + row0] = lacc[0];
    }
    if (row1 < NPTS) {
        #pragma unroll
        for (int n = 0; n < 8; n++) {
            unsigned u; PACKH2(u, o[n][2], o[n][3]);
            op[row1*32 + n*4 + tg] = u;
        }
        if (tg == 0) g_l[pidx*NPTS + row1] = lacc[2];
    }
}

// ---------------------------------------------------------------------------
// out[n][a*64+d] = sum_kh wgt * (O_s0 + O_s1) / (l_s0 + l_s1)
// ---------------------------------------------------------------------------
__global__ __launch_bounds__(256) void combine_kernel(float* __restrict__ out)
{
    int idx4 = blockIdx.x * blockDim.x + threadIdx.x;
    int e  = idx4 * 4;
    int n  = e >> 8;
    int o  = e & 255;
    int a  = o >> 6, dd = o & 63;
    float4 acc = make_float4(0.f, 0.f, 0.f, 0.f);
    #pragma unroll
    for (int khh = 0; khh < 4; khh++) {
        int hh = ((a - khh + 1) & 3) - 1;
        float wgt = (hh == 2) ? 2.0f : 1.0f;
        int p0 = (a*4 + khh)*2;
        float l = g_l[p0*NPTS + n] + g_l[(p0+1)*NPTS + n];
        float w = wgt / l;
        const unsigned* pp = g_part + ((long)p0*NPTS + n)*32 + (dd >> 1);
        uint2 u1 = *(const uint2*)pp;
        uint2 u2 = *(const uint2*)(pp + (long)NPTS*32);
        float2 a0 = __half22float2(*(__half2*)&u1.x);
        float2 a1 = __half22float2(*(__half2*)&u1.y);
        float2 b0 = __half22float2(*(__half2*)&u2.x);
        float2 b1 = __half22float2(*(__half2*)&u2.y);
        acc.x += w*(a0.x + b0.x);
        acc.y += w*(a0.y + b0.y);
        acc.z += w*(a1.x + b1.x);
        acc.w += w*(a1.y + b1.y);
    }
    *(float4*)&out[e] = acc;
}

// ---------------------------------------------------------------------------
extern "C" void kernel_launch(void* const* d_in, const int* in_sizes, int n_in,
                              void* d_out, int out_size)
{
    const float* x  = (const float*)d_in[0];
    const float* Wq = (const float*)d_in[1];
    const float* bq = (const float*)d_in[2];
    const float* Wk = (const float*)d_in[3];
    const float* bk = (const float*)d_in[4];
    const float* Wv = (const float*)d_in[5];
    const float* bv = (const float*)d_in[6];
    float* out = (float*)d_out;

    cudaFuncSetAttribute(attn_kernel,
                         cudaFuncAttributeMaxDynamicSharedMemorySize, SMEM_ATTN);

    convert_kernel<<<(NPTS*CIN/8 + 3*ODIM*32 + 255)/256, 256>>>(x, Wq, Wk, Wv);
    proj_kernel<<<dim3(13, 4, 3), 256>>>(bq, bk, bv);
    vtilde_kernel<<<(NH*NKT*32*16 + 255)/256, 256>>>();
    attn_kernel<<<dim3(13, 16, 2), 256, SMEM_ATTN>>>();
    combine_kernel<<<(NPTS*ODIM/4 + 255)/256, 256>>>(out);
}